// round 11
// baseline (speedup 1.0000x reference)
#include <cuda_runtime.h>
#include <cuda_bf16.h>
#include <cstdint>

#define Bn 4
#define Sn 1024
#define Hn 1024
#define NHn 16
#define HDn 64
#define LOG2E 1.4426950408889634f
#define SCALE_L2E (0.125f * 1.4426950408889634f)
#define VERB_L2E (2.0f * 1.4426950408889634f)

#define Mtot (Bn*Sn)     // 4096
#define W_ELEMS (Hn*Hn)  // 1048576

// ---------------- scratch (allocation-free) ----------------
__device__ float g_colb[Bn*Sn];
__device__ int   g_vt[Bn*Sn];

__device__ __nv_bfloat16 g_xhi[Mtot*Hn];
__device__ __nv_bfloat16 g_xlo[Mtot*Hn];
__device__ __nv_bfloat16 g_qhi[Mtot*Hn];
__device__ __nv_bfloat16 g_qlo[Mtot*Hn];
__device__ __nv_bfloat16 g_khi[Mtot*Hn];
__device__ __nv_bfloat16 g_klo[Mtot*Hn];
__device__ __nv_bfloat16 g_vhi[Mtot*Hn];
__device__ __nv_bfloat16 g_vlo[Mtot*Hn];
__device__ __nv_bfloat16 g_ohi[Mtot*Hn];
__device__ __nv_bfloat16 g_olo[Mtot*Hn];
__device__ __nv_bfloat16 g_wthi[4*W_ELEMS];   // W^T per matrix: [n][k]
__device__ __nv_bfloat16 g_wtlo[4*W_ELEMS];

// ---------------- PTX helpers (family-portable only) ----------------
__device__ __forceinline__ uint32_t smem_to_u32(const void* p) {
    uint32_t a;
    asm("{ .reg .u64 t; cvta.to.shared.u64 t, %1; cvt.u32.u64 %0, t; }" : "=r"(a) : "l"(p));
    return a;
}
__device__ __forceinline__ void ldsm_x4(uint32_t addr, uint32_t& r0, uint32_t& r1,
                                        uint32_t& r2, uint32_t& r3) {
    asm volatile("ldmatrix.sync.aligned.m8n8.x4.shared.b16 {%0,%1,%2,%3}, [%4];"
        : "=r"(r0), "=r"(r1), "=r"(r2), "=r"(r3) : "r"(addr));
}
__device__ __forceinline__ void ldsm_x4_t(uint32_t addr, uint32_t& r0, uint32_t& r1,
                                          uint32_t& r2, uint32_t& r3) {
    asm volatile("ldmatrix.sync.aligned.m8n8.x4.trans.shared.b16 {%0,%1,%2,%3}, [%4];"
        : "=r"(r0), "=r"(r1), "=r"(r2), "=r"(r3) : "r"(addr));
}
__device__ __forceinline__ void mma16816(float* c, uint32_t a0, uint32_t a1,
                                         uint32_t a2, uint32_t a3,
                                         uint32_t b0, uint32_t b1) {
    asm volatile(
        "mma.sync.aligned.m16n8k16.row.col.f32.bf16.bf16.f32 "
        "{%0,%1,%2,%3}, {%4,%5,%6,%7}, {%8,%9}, {%0,%1,%2,%3};"
        : "+f"(c[0]), "+f"(c[1]), "+f"(c[2]), "+f"(c[3])
        : "r"(a0), "r"(a1), "r"(a2), "r"(a3), "r"(b0), "r"(b1));
}
__device__ __forceinline__ void cp_async16(uint32_t saddr, const void* gptr) {
    asm volatile("cp.async.cg.shared.global [%0], [%1], 16;" :: "r"(saddr), "l"(gptr));
}
#define CP_COMMIT() asm volatile("cp.async.commit_group;")
#define CP_WAIT0()  asm volatile("cp.async.wait_group 0;")
#define CP_WAIT1()  asm volatile("cp.async.wait_group 1;")

__device__ __forceinline__ float ex2f(float x) {
    float y;
    asm("ex2.approx.ftz.f32 %0, %1;" : "=f"(y) : "f"(x));
    return y;
}

// SW128 swizzled address within a tile of 128B rows
__device__ __forceinline__ uint32_t swz(uint32_t base, int row, int kb) {
    uint32_t bo = (uint32_t)(row * 128 + kb);
    return base + (bo ^ ((bo >> 3) & 0x70));
}
__device__ __forceinline__ uint32_t swzoff(int row, int kb) {
    uint32_t bo = (uint32_t)(row * 128 + kb);
    return bo ^ ((bo >> 3) & 0x70);
}
__device__ __forceinline__ uint32_t pack_bf16(float a, float b) {
    __nv_bfloat162 h = __float22bfloat162_rn(make_float2(a, b));
    return *(uint32_t*)&h;
}

// ---------------- morpho preprocessing ----------------
__global__ void morpho_kernel(const int* __restrict__ morpho) {
    int b = blockIdx.x;
    int i = threadIdx.x;
    const int* mrow = morpho + b * Sn;
    __shared__ unsigned char isv[Sn];
    __shared__ int anyv;
    if (i == 0) anyv = 0;
    __syncthreads();
    int t = mrow[i];
    unsigned char iv = (t == 2);
    isv[i] = iv;
    if (iv) anyv = 1;
    g_colb[b*Sn + i] = (1.5f*0.5f) * (t == 0) + (1.2f*0.3f) * (t == 1);
    __syncthreads();
    int nearest = -1;
    if (anyv) {
        for (int d = 0; d < Sn; d++) {
            int jl = i - d;
            if (jl >= 0 && isv[jl]) { nearest = jl; break; }
            int jr = i + d;
            if (jr < Sn && isv[jr]) { nearest = jr; break; }
        }
    }
    g_vt[b*Sn + i] = nearest;
}

// ---------------- conversion kernels ----------------
__global__ void convert_split(const float* __restrict__ src,
                              __nv_bfloat16* __restrict__ hi,
                              __nv_bfloat16* __restrict__ lo, int n) {
    int idx = (blockIdx.x * blockDim.x + threadIdx.x) * 4;
    if (idx < n) {
        float4 x = *(const float4*)(src + idx);
        __nv_bfloat16 h0 = __float2bfloat16_rn(x.x);
        __nv_bfloat16 h1 = __float2bfloat16_rn(x.y);
        __nv_bfloat16 h2 = __float2bfloat16_rn(x.z);
        __nv_bfloat16 h3 = __float2bfloat16_rn(x.w);
        __nv_bfloat162 hp0, hp1, lp0, lp1;
        hp0.x = h0; hp0.y = h1; hp1.x = h2; hp1.y = h3;
        lp0.x = __float2bfloat16_rn(x.x - __bfloat162float(h0));
        lp0.y = __float2bfloat16_rn(x.y - __bfloat162float(h1));
        lp1.x = __float2bfloat16_rn(x.z - __bfloat162float(h2));
        lp1.y = __float2bfloat16_rn(x.w - __bfloat162float(h3));
        *(__nv_bfloat162*)(hi + idx) = hp0;
        *(__nv_bfloat162*)(hi + idx + 2) = hp1;
        *(__nv_bfloat162*)(lo + idx) = lp0;
        *(__nv_bfloat162*)(lo + idx + 2) = lp1;
    }
}

__global__ void transpose_convert_w(const float* __restrict__ Wq, const float* __restrict__ Wk,
                                    const float* __restrict__ Wv, const float* __restrict__ Wo) {
    __shared__ float t[32][33];
    int z = blockIdx.z;
    const float* W = (z == 0) ? Wq : (z == 1) ? Wk : (z == 2) ? Wv : Wo;
    __nv_bfloat16* whi = g_wthi + (size_t)z * W_ELEMS;
    __nv_bfloat16* wlo = g_wtlo + (size_t)z * W_ELEMS;
    int n0 = blockIdx.x * 32, k0 = blockIdx.y * 32;
    int tx = threadIdx.x, ty = threadIdx.y;
    #pragma unroll
    for (int i = 0; i < 4; i++) {
        int kr = ty + i * 8;
        t[kr][tx] = W[(size_t)(k0 + kr) * Hn + n0 + tx];
    }
    __syncthreads();
    #pragma unroll
    for (int i = 0; i < 4; i++) {
        int nr = ty + i * 8;
        float x = t[tx][nr];
        __nv_bfloat16 h = __float2bfloat16_rn(x);
        whi[(size_t)(n0 + nr) * Hn + k0 + tx] = h;
        wlo[(size_t)(n0 + nr) * Hn + k0 + tx] = __float2bfloat16_rn(x - __bfloat162float(h));
    }
}

// ---------------- mma.sync GEMM: 2 CTAs/SM, packed hi|lo rows, K-chunk 32 ----------------
// smem row (128B) = [hi 64B | lo 64B] for K=32 chunk. Stage = A(16KB)+B(16KB) = 32KB.
// 2 stages = 64KB/CTA -> 2 CTAs/SM. Frag regs minimized by reloading A-lo over A-hi.
#define GQ_ATILE 16384
#define GQ_STAGE 32768
#define GQ_SMEM  (2*GQ_STAGE)   // 65536
#define GQ_NCHUNK 32

template<int BF16OUT>
__device__ __forceinline__ void gemm_mma_body(
    const __nv_bfloat16* __restrict__ Ahi, const __nv_bfloat16* __restrict__ Alo,
    const __nv_bfloat16* __restrict__ Bhi, const __nv_bfloat16* __restrict__ Blo,
    const float* __restrict__ bias, float* __restrict__ C,
    __nv_bfloat16* __restrict__ Chi, __nv_bfloat16* __restrict__ Clo)
{
    extern __shared__ char smc[];
    uint32_t smb = smem_to_u32(smc);

    int tid = threadIdx.x;
    int wid = tid >> 5, lane = tid & 31;
    int r0 = blockIdx.y * 128;
    int c0 = blockIdx.x * 128;
    int wm = (wid >> 2) * 64;
    int wn = (wid & 3) * 32;

    int la = lane & 7, qa = lane >> 3;
    int rowoff_a = (qa & 1) * 8 + la;
    int kboff_a  = (qa >> 1) * 16;
    int rowoff_b = (qa >> 1) * 8 + la;
    int kboff_b  = (qa & 1) * 16;

    float acc[4][4][4];
    #pragma unroll
    for (int mf = 0; mf < 4; mf++)
        #pragma unroll
        for (int nf = 0; nf < 4; nf++)
            #pragma unroll
            for (int j = 0; j < 4; j++) acc[mf][nf][j] = 0.f;

    auto issue_chunk = [&](uint32_t base, int ch) {
        int k0 = ch * 32;
        #pragma unroll
        for (int r = 0; r < 4; r++) {
            int idx = tid + 256 * r;
            int row = idx >> 3, c16 = idx & 7;
            uint32_t sw = swzoff(row, c16 * 16);
            int kcol = (c16 & 3) * 8;
            const __nv_bfloat16* sA = (c16 < 4) ? (Ahi + (size_t)(r0 + row) * Hn + k0 + kcol)
                                                : (Alo + (size_t)(r0 + row) * Hn + k0 + kcol);
            const __nv_bfloat16* sB = (c16 < 4) ? (Bhi + (size_t)(c0 + row) * Hn + k0 + kcol)
                                                : (Blo + (size_t)(c0 + row) * Hn + k0 + kcol);
            cp_async16(base + sw,            sA);
            cp_async16(base + GQ_ATILE + sw, sB);
        }
        CP_COMMIT();
    };

    issue_chunk(smb, 0);

    for (int ch = 0; ch < GQ_NCHUNK; ch++) {
        if (ch + 1 < GQ_NCHUNK) {
            issue_chunk(smb + (uint32_t)((ch + 1) & 1) * GQ_STAGE, ch + 1);
            CP_WAIT1();
        } else {
            CP_WAIT0();
        }
        __syncthreads();

        uint32_t tA = smb + (uint32_t)(ch & 1) * GQ_STAGE;
        uint32_t tB = tA + GQ_ATILE;

        #pragma unroll
        for (int ks = 0; ks < 2; ks++) {
            int ko = ks * 32;
            uint32_t A[4][4], Bh[2][4], Bl[2][4];
            #pragma unroll
            for (int mf = 0; mf < 4; mf++)
                ldsm_x4(swz(tA, wm + mf * 16 + rowoff_a, ko + kboff_a),
                        A[mf][0], A[mf][1], A[mf][2], A[mf][3]);
            #pragma unroll
            for (int g = 0; g < 2; g++) {
                int rwb = wn + g * 16 + rowoff_b;
                ldsm_x4(swz(tB, rwb, ko + kboff_b),      Bh[g][0], Bh[g][1], Bh[g][2], Bh[g][3]);
                ldsm_x4(swz(tB, rwb, 64 + ko + kboff_b), Bl[g][0], Bl[g][1], Bl[g][2], Bl[g][3]);
            }
            // pass hi*hi
            #pragma unroll
            for (int mf = 0; mf < 4; mf++)
                #pragma unroll
                for (int nf = 0; nf < 4; nf++)
                    mma16816(acc[mf][nf], A[mf][0], A[mf][1], A[mf][2], A[mf][3],
                             Bh[nf >> 1][(nf & 1) * 2], Bh[nf >> 1][(nf & 1) * 2 + 1]);
            // pass hi*lo
            #pragma unroll
            for (int mf = 0; mf < 4; mf++)
                #pragma unroll
                for (int nf = 0; nf < 4; nf++)
                    mma16816(acc[mf][nf], A[mf][0], A[mf][1], A[mf][2], A[mf][3],
                             Bl[nf >> 1][(nf & 1) * 2], Bl[nf >> 1][(nf & 1) * 2 + 1]);
            // reload A-lo over A-hi regs, pass lo*hi
            #pragma unroll
            for (int mf = 0; mf < 4; mf++)
                ldsm_x4(swz(tA, wm + mf * 16 + rowoff_a, 64 + ko + kboff_a),
                        A[mf][0], A[mf][1], A[mf][2], A[mf][3]);
            #pragma unroll
            for (int mf = 0; mf < 4; mf++)
                #pragma unroll
                for (int nf = 0; nf < 4; nf++)
                    mma16816(acc[mf][nf], A[mf][0], A[mf][1], A[mf][2], A[mf][3],
                             Bh[nf >> 1][(nf & 1) * 2], Bh[nf >> 1][(nf & 1) * 2 + 1]);
        }
        __syncthreads();
    }

    #pragma unroll
    for (int mf = 0; mf < 4; mf++) {
        int row = r0 + wm + mf * 16 + (lane >> 2);
        #pragma unroll
        for (int nf = 0; nf < 4; nf++) {
            int col = c0 + wn + nf * 8 + 2 * (lane & 3);
            float b0 = bias[col], b1 = bias[col + 1];
            float v0 = acc[mf][nf][0] + b0, v1 = acc[mf][nf][1] + b1;
            float v2 = acc[mf][nf][2] + b0, v3 = acc[mf][nf][3] + b1;
            if (BF16OUT) {
                __nv_bfloat162 h0 = __float22bfloat162_rn(make_float2(v0, v1));
                __nv_bfloat162 l0 = __float22bfloat162_rn(make_float2(
                    v0 - __bfloat162float(h0.x), v1 - __bfloat162float(h0.y)));
                __nv_bfloat162 h1 = __float22bfloat162_rn(make_float2(v2, v3));
                __nv_bfloat162 l1 = __float22bfloat162_rn(make_float2(
                    v2 - __bfloat162float(h1.x), v3 - __bfloat162float(h1.y)));
                *(__nv_bfloat162*)(Chi + (size_t)row * Hn + col)       = h0;
                *(__nv_bfloat162*)(Clo + (size_t)row * Hn + col)       = l0;
                *(__nv_bfloat162*)(Chi + (size_t)(row + 8) * Hn + col) = h1;
                *(__nv_bfloat162*)(Clo + (size_t)(row + 8) * Hn + col) = l1;
            } else {
                *(float2*)(C + (size_t)row * Hn + col)       = make_float2(v0, v1);
                *(float2*)(C + (size_t)(row + 8) * Hn + col) = make_float2(v2, v3);
            }
        }
    }
}

__global__ void __launch_bounds__(256, 2) qkv_tc(
    const float* __restrict__ bq, const float* __restrict__ bk, const float* __restrict__ bv)
{
    int z = blockIdx.z;
    const float* bias = (z == 0) ? bq : (z == 1) ? bk : bv;
    __nv_bfloat16* Chi = (z == 0) ? g_qhi : (z == 1) ? g_khi : g_vhi;
    __nv_bfloat16* Clo = (z == 0) ? g_qlo : (z == 1) ? g_klo : g_vlo;
    gemm_mma_body<1>(g_xhi, g_xlo,
                     g_wthi + (size_t)z * W_ELEMS, g_wtlo + (size_t)z * W_ELEMS,
                     bias, nullptr, Chi, Clo);
}

__global__ void __launch_bounds__(256, 2) out_tc(const float* __restrict__ bo, float* __restrict__ C)
{
    gemm_mma_body<0>(g_ohi, g_olo,
                     g_wthi + (size_t)3 * W_ELEMS, g_wtlo + (size_t)3 * W_ELEMS,
                     bo, C, nullptr, nullptr);
}

// ---------------- flash attention: 128 threads / 4 warps / 64 q-rows, 2 CTAs/SM ----------------
#define AT_KVBUF 32768
#define AT_SMEM (4096 + 2*AT_KVBUF)  // 69632

__device__ __forceinline__ void qk6(float* c0, float* c1, uint32_t* Q4a, uint32_t* Q4b,
                                    uint32_t* kh, uint32_t* kl) {
    mma16816(c0, Q4a[0], Q4a[1], Q4a[2], Q4a[3], kh[0], kh[1]);
    mma16816(c1, Q4a[0], Q4a[1], Q4a[2], Q4a[3], kh[2], kh[3]);
    mma16816(c0, Q4a[0], Q4a[1], Q4a[2], Q4a[3], kl[0], kl[1]);
    mma16816(c1, Q4a[0], Q4a[1], Q4a[2], Q4a[3], kl[2], kl[3]);
    mma16816(c0, Q4b[0], Q4b[1], Q4b[2], Q4b[3], kh[0], kh[1]);
    mma16816(c1, Q4b[0], Q4b[1], Q4b[2], Q4b[3], kh[2], kh[3]);
}

__global__ void __launch_bounds__(128) attn_mma() {
    extern __shared__ char smc[];
    uint32_t smb = smem_to_u32(smc);
    float* colb_sm = (float*)smc;
    uint32_t bufb = smb + 4096;

    int tid = threadIdx.x;
    int wid = tid >> 5, lane = tid & 31;
    int b = blockIdx.z, h = blockIdx.y;
    int i0 = blockIdx.x * 64;

    int la = lane & 7, qa = lane >> 3;
    int roa = (qa & 1) * 8 + la, kba = (qa >> 1) * 16;
    int rob = (qa >> 1) * 8 + la, kbb = (qa & 1) * 16;

    // stage colb pre-scaled by log2e
    #pragma unroll
    for (int r = 0; r < 8; r++)
        colb_sm[tid + 128 * r] = g_colb[b * Sn + tid + 128 * r] * LOG2E;

    // stage Q tile [64 x 64] hi/lo into KV buffer region, extract to regs
    {
        const __nv_bfloat16* qhb = g_qhi + (size_t)(b * Sn + i0) * Hn + h * HDn;
        const __nv_bfloat16* qlb = g_qlo + (size_t)(b * Sn + i0) * Hn + h * HDn;
        #pragma unroll
        for (int r = 0; r < 4; r++) {
            int idx = tid + 128 * r;
            int row = idx >> 3, c16 = idx & 7;
            uint32_t sw = swzoff(row, c16 * 16);
            size_t ga = (size_t)row * Hn + c16 * 8;
            *(uint4*)(smc + 4096 + sw)        = *(const uint4*)(qhb + ga);
            *(uint4*)(smc + 4096 + 8192 + sw) = *(const uint4*)(qlb + ga);
        }
    }
    __syncthreads();
    uint32_t Qh[4][4], Ql[4][4];
    #pragma unroll
    for (int kd = 0; kd < 4; kd++) {
        int rw = wid * 16 + roa;
        ldsm_x4(swz(bufb, rw, kd * 32 + kba),        Qh[kd][0], Qh[kd][1], Qh[kd][2], Qh[kd][3]);
        ldsm_x4(swz(bufb + 8192, rw, kd * 32 + kba), Ql[kd][0], Ql[kd][1], Ql[kd][2], Ql[kd][3]);
    }
    __syncthreads();

    int r_g = i0 + wid * 16 + (lane >> 2);
    int vt0 = g_vt[b * Sn + r_g];
    int vt1 = g_vt[b * Sn + r_g + 8];

    float m0 = -3.0e38f, m1 = -3.0e38f, l0 = 0.f, l1 = 0.f;
    float acc[8][4];
    #pragma unroll
    for (int t = 0; t < 8; t++)
        #pragma unroll
        for (int j = 0; j < 4; j++) acc[t][j] = 0.f;

    const __nv_bfloat16* khb = g_khi + (size_t)b * Sn * Hn + h * HDn;
    const __nv_bfloat16* klb = g_klo + (size_t)b * Sn * Hn + h * HDn;
    const __nv_bfloat16* vhb = g_vhi + (size_t)b * Sn * Hn + h * HDn;
    const __nv_bfloat16* vlb = g_vlo + (size_t)b * Sn * Hn + h * HDn;

    auto issue_kv = [&](uint32_t base, int j0) {
        #pragma unroll
        for (int r = 0; r < 4; r++) {
            int idx = tid + 128 * r;
            int row = idx >> 3, c16 = idx & 7;
            uint32_t sw = swzoff(row, c16 * 16);
            size_t go = (size_t)(j0 + row) * Hn + c16 * 8;
            cp_async16(base + sw,         khb + go);
            cp_async16(base + 8192 + sw,  klb + go);
            cp_async16(base + 16384 + sw, vhb + go);
            cp_async16(base + 24576 + sw, vlb + go);
        }
        CP_COMMIT();
    };

    issue_kv(bufb, 0);

    for (int jt = 0; jt < Sn / 64; jt++) {
        if (jt + 1 < Sn / 64) {
            issue_kv(bufb + ((jt + 1) & 1) * AT_KVBUF, (jt + 1) * 64);
            CP_WAIT1();
        } else {
            CP_WAIT0();
        }
        __syncthreads();

        uint32_t cb = bufb + (jt & 1) * AT_KVBUF;
        uint32_t Kh = cb, Kl = cb + 8192, Vh = cb + 16384, Vl = cb + 24576;

        // S = Q K^T (3-pass hi/lo)
        float s[8][4];
        #pragma unroll
        for (int t = 0; t < 8; t++)
            #pragma unroll
            for (int j = 0; j < 4; j++) s[t][j] = 0.f;
        #pragma unroll
        for (int kd = 0; kd < 4; kd++) {
            #pragma unroll
            for (int ng = 0; ng < 4; ng++) {
                uint32_t kh[4], kl[4];
                ldsm_x4(swz(Kh, ng * 16 + rob, kd * 32 + kbb), kh[0], kh[1], kh[2], kh[3]);
                ldsm_x4(swz(Kl, ng * 16 + rob, kd * 32 + kbb), kl[0], kl[1], kl[2], kl[3]);
                qk6(s[2*ng], s[2*ng+1], Qh[kd], Ql[kd], kh, kl);
            }
        }

        // scale + bias (log2 domain) + online softmax
        float rmax0 = -3.0e38f, rmax1 = -3.0e38f;
        #pragma unroll
        for (int t = 0; t < 8; t++) {
            int jc = jt * 64 + t * 8 + (lane & 3) * 2;
            float cb0 = colb_sm[jc], cb1 = colb_sm[jc + 1];
            s[t][0] = s[t][0] * SCALE_L2E + cb0 + (jc     == vt0 ? VERB_L2E : 0.f);
            s[t][1] = s[t][1] * SCALE_L2E + cb1 + (jc + 1 == vt0 ? VERB_L2E : 0.f);
            s[t][2] = s[t][2] * SCALE_L2E + cb0 + (jc     == vt1 ? VERB_L2E : 0.f);
            s[t][3] = s[t][3] * SCALE_L2E + cb1 + (jc + 1 == vt1 ? VERB_L2E : 0.f);
            rmax0 = fmaxf(rmax0, fmaxf(s[t][0], s[t][1]));
            rmax1 = fmaxf(rmax1, fmaxf(s[t][2], s[t][3]));
        }
        rmax0 = fmaxf(rmax0, __shfl_xor_sync(0xffffffffu, rmax0, 1));
        rmax0 = fmaxf(rmax0, __shfl_xor_sync(0xffffffffu, rmax0, 2));
        rmax1 = fmaxf(rmax1, __shfl_xor_sync(0xffffffffu, rmax1, 1));
        rmax1 = fmaxf(rmax1, __shfl_xor_sync(0xffffffffu, rmax1, 2));
        float mn0 = fmaxf(m0, rmax0), mn1 = fmaxf(m1, rmax1);
        float cr0 = ex2f(m0 - mn0), cr1 = ex2f(m1 - mn1);
        m0 = mn0; m1 = mn1;

        float sum0 = 0.f, sum1 = 0.f;
        uint32_t Ph[4][4], Pl[4][4];
        #pragma unroll
        for (int g = 0; g < 4; g++) {
            #pragma unroll
            for (int hh = 0; hh < 2; hh++) {
                int t = 2 * g + hh;
                float p0 = ex2f(s[t][0] - mn0);
                float p1 = ex2f(s[t][1] - mn0);
                float p2 = ex2f(s[t][2] - mn1);
                float p3 = ex2f(s[t][3] - mn1);
                sum0 += p0 + p1; sum1 += p2 + p3;
                uint32_t h01 = pack_bf16(p0, p1);
                uint32_t h23 = pack_bf16(p2, p3);
                __nv_bfloat162 hh01 = *(__nv_bfloat162*)&h01;
                __nv_bfloat162 hh23 = *(__nv_bfloat162*)&h23;
                uint32_t l01 = pack_bf16(p0 - __bfloat162float(hh01.x), p1 - __bfloat162float(hh01.y));
                uint32_t l23 = pack_bf16(p2 - __bfloat162float(hh23.x), p3 - __bfloat162float(hh23.y));
                Ph[g][hh * 2]     = h01;
                Ph[g][hh * 2 + 1] = h23;
                Pl[g][hh * 2]     = l01;
                Pl[g][hh * 2 + 1] = l23;
            }
        }
        sum0 += __shfl_xor_sync(0xffffffffu, sum0, 1);
        sum0 += __shfl_xor_sync(0xffffffffu, sum0, 2);
        sum1 += __shfl_xor_sync(0xffffffffu, sum1, 1);
        sum1 += __shfl_xor_sync(0xffffffffu, sum1, 2);
        l0 = l0 * cr0 + sum0;
        l1 = l1 * cr1 + sum1;
        #pragma unroll
        for (int t = 0; t < 8; t++) {
            acc[t][0] *= cr0; acc[t][1] *= cr0;
            acc[t][2] *= cr1; acc[t][3] *= cr1;
        }

        // O += P V (3-pass), V^T fragments via ldmatrix.trans
        #pragma unroll
        for (int g = 0; g < 4; g++) {
            #pragma unroll
            for (int gd = 0; gd < 4; gd++) {
                uint32_t vh[4], vl[4];
                ldsm_x4_t(swz(Vh, g * 16 + roa, gd * 32 + kba), vh[0], vh[1], vh[2], vh[3]);
                ldsm_x4_t(swz(Vl, g * 16 + roa, gd * 32 + kba), vl[0], vl[1], vl[2], vl[3]);
                float* c0 = acc[2*gd];
                float* c1 = acc[2*gd+1];
                mma16816(c0, Ph[g][0], Ph[g][1], Ph[g][2], Ph[g][3], vh[0], vh[1]);
                mma16816(c1, Ph[g][0], Ph[g][1], Ph[g][2], Ph[g][3], vh[2], vh[3]);
                mma16816(c0, Ph[g][0], Ph[g][1], Ph[g][2], Ph[g][3], vl[0], vl[1]);
                mma16816(c1, Ph[g][0], Ph[g][1], Ph[g][2], Ph[g][3], vl[2], vl[3]);
                mma16816(c0, Pl[g][0], Pl[g][1], Pl[g][2], Pl[g][3], vh[0], vh[1]);
                mma16816(c1, Pl[g][0], Pl[g][1], Pl[g][2], Pl[g][3], vh[2], vh[3]);
            }
        }
        __syncthreads();
    }

    // epilogue: normalize, split hi/lo, store
    float inv0 = 1.f / l0, inv1 = 1.f / l1;
    __nv_bfloat16* ohb = g_ohi + (size_t)(b * Sn + r_g) * Hn + h * HDn;
    __nv_bfloat16* olb = g_olo + (size_t)(b * Sn + r_g) * Hn + h * HDn;
    #pragma unroll
    for (int t = 0; t < 8; t++) {
        int d = t * 8 + (lane & 3) * 2;
        float v0 = acc[t][0] * inv0, v1 = acc[t][1] * inv0;
        float v2 = acc[t][2] * inv1, v3 = acc[t][3] * inv1;
        __nv_bfloat162 h0 = __float22bfloat162_rn(make_float2(v0, v1));
        __nv_bfloat162 l0v = __float22bfloat162_rn(make_float2(
            v0 - __bfloat162float(h0.x), v1 - __bfloat162float(h0.y)));
        __nv_bfloat162 h1 = __float22bfloat162_rn(make_float2(v2, v3));
        __nv_bfloat162 l1v = __float22bfloat162_rn(make_float2(
            v2 - __bfloat162float(h1.x), v3 - __bfloat162float(h1.y)));
        *(__nv_bfloat162*)(ohb + d)                  = h0;
        *(__nv_bfloat162*)(olb + d)                  = l0v;
        *(__nv_bfloat162*)(ohb + (size_t)8 * Hn + d) = h1;
        *(__nv_bfloat162*)(olb + (size_t)8 * Hn + d) = l1v;
    }
}

// ---------------- launch ----------------
extern "C" void kernel_launch(void* const* d_in, const int* in_sizes, int n_in,
                              void* d_out, int out_size) {
    const float* hidden = (const float*)d_in[0];
    const int*   morpho = (const int*)d_in[1];
    const float* Wq = (const float*)d_in[2];
    const float* bq = (const float*)d_in[3];
    const float* Wk = (const float*)d_in[4];
    const float* bk = (const float*)d_in[5];
    const float* Wv = (const float*)d_in[6];
    const float* bv = (const float*)d_in[7];
    const float* Wo = (const float*)d_in[8];
    const float* bo = (const float*)d_in[9];
    float* out = (float*)d_out;

    cudaFuncSetAttribute(qkv_tc,
                         cudaFuncAttributeMaxDynamicSharedMemorySize, GQ_SMEM);
    cudaFuncSetAttribute(out_tc,
                         cudaFuncAttributeMaxDynamicSharedMemorySize, GQ_SMEM);
    cudaFuncSetAttribute(attn_mma,
                         cudaFuncAttributeMaxDynamicSharedMemorySize, AT_SMEM);

    static __nv_bfloat16 *xhi_p = nullptr, *xlo_p = nullptr;
    if (!xhi_p) {
        cudaGetSymbolAddress((void**)&xhi_p, g_xhi);
        cudaGetSymbolAddress((void**)&xlo_p, g_xlo);
    }

    morpho_kernel<<<Bn, Sn>>>(morpho);
    convert_split<<<(Mtot*Hn/4 + 255) / 256, 256>>>(hidden, xhi_p, xlo_p, Mtot*Hn);
    transpose_convert_w<<<dim3(32, 32, 4), dim3(32, 8)>>>(Wq, Wk, Wv, Wo);
    qkv_tc<<<dim3(Hn/128, Mtot/128, 3), 256, GQ_SMEM>>>(bq, bk, bv);
    attn_mma<<<dim3(Sn/64, NHn, Bn), 128, AT_SMEM>>>();
    out_tc<<<dim3(Hn/128, Mtot/128, 1), 256, GQ_SMEM>>>(bo, out);
}

// round 13
// speedup vs baseline: 1.7596x; 1.7596x over previous
#include <cuda_runtime.h>
#include <cuda_fp16.h>
#include <cstdint>

#define Bn 4
#define Sn 1024
#define Hn 1024
#define NHn 16
#define HDn 64
#define LOG2E 1.4426950408889634f
#define SCALE_L2E (0.125f * 1.4426950408889634f)
#define VERB_L2E (2.0f * 1.4426950408889634f)

#define Mtot (Bn*Sn)     // 4096
#define W_ELEMS (Hn*Hn)  // 1048576

// ---------------- scratch (allocation-free) ----------------
__device__ float g_colb[Bn*Sn];
__device__ int   g_vt[Bn*Sn];

__device__ __half g_xhi[Mtot*Hn];
__device__ __half g_xlo[Mtot*Hn];
__device__ __half g_qhi[Mtot*Hn];
__device__ __half g_qlo[Mtot*Hn];
__device__ __half g_khi[Mtot*Hn];
__device__ __half g_klo[Mtot*Hn];
__device__ __half g_v1 [Mtot*Hn];     // V single fp16
__device__ __half g_o1 [Mtot*Hn];     // attention output single fp16
__device__ __half g_wthi[4*W_ELEMS];  // W^T per matrix: [n][k]
__device__ __half g_wtlo[4*W_ELEMS];

// ---------------- PTX helpers (family-portable only) ----------------
__device__ __forceinline__ uint32_t smem_to_u32(const void* p) {
    uint32_t a;
    asm("{ .reg .u64 t; cvta.to.shared.u64 t, %1; cvt.u32.u64 %0, t; }" : "=r"(a) : "l"(p));
    return a;
}
__device__ __forceinline__ void ldsm_x4(uint32_t addr, uint32_t& r0, uint32_t& r1,
                                        uint32_t& r2, uint32_t& r3) {
    asm volatile("ldmatrix.sync.aligned.m8n8.x4.shared.b16 {%0,%1,%2,%3}, [%4];"
        : "=r"(r0), "=r"(r1), "=r"(r2), "=r"(r3) : "r"(addr));
}
__device__ __forceinline__ void ldsm_x4_t(uint32_t addr, uint32_t& r0, uint32_t& r1,
                                          uint32_t& r2, uint32_t& r3) {
    asm volatile("ldmatrix.sync.aligned.m8n8.x4.trans.shared.b16 {%0,%1,%2,%3}, [%4];"
        : "=r"(r0), "=r"(r1), "=r"(r2), "=r"(r3) : "r"(addr));
}
__device__ __forceinline__ void mma16816(float* c, uint32_t a0, uint32_t a1,
                                         uint32_t a2, uint32_t a3,
                                         uint32_t b0, uint32_t b1) {
    asm volatile(
        "mma.sync.aligned.m16n8k16.row.col.f32.f16.f16.f32 "
        "{%0,%1,%2,%3}, {%4,%5,%6,%7}, {%8,%9}, {%0,%1,%2,%3};"
        : "+f"(c[0]), "+f"(c[1]), "+f"(c[2]), "+f"(c[3])
        : "r"(a0), "r"(a1), "r"(a2), "r"(a3), "r"(b0), "r"(b1));
}
__device__ __forceinline__ void cp_async16(uint32_t saddr, const void* gptr) {
    asm volatile("cp.async.cg.shared.global [%0], [%1], 16;" :: "r"(saddr), "l"(gptr));
}
#define CP_COMMIT() asm volatile("cp.async.commit_group;")
#define CP_WAIT0()  asm volatile("cp.async.wait_group 0;")
#define CP_WAIT1()  asm volatile("cp.async.wait_group 1;")

__device__ __forceinline__ float ex2f(float x) {
    float y;
    asm("ex2.approx.ftz.f32 %0, %1;" : "=f"(y) : "f"(x));
    return y;
}

// SW128 swizzled address within a tile of 128B rows
__device__ __forceinline__ uint32_t swz(uint32_t base, int row, int kb) {
    uint32_t bo = (uint32_t)(row * 128 + kb);
    return base + (bo ^ ((bo >> 3) & 0x70));
}
__device__ __forceinline__ uint32_t swzoff(int row, int kb) {
    uint32_t bo = (uint32_t)(row * 128 + kb);
    return bo ^ ((bo >> 3) & 0x70);
}
__device__ __forceinline__ uint32_t pack_f16(float a, float b) {
    __half2 h = __floats2half2_rn(a, b);
    return *(uint32_t*)&h;
}

// ---------------- morpho preprocessing ----------------
__global__ void morpho_kernel(const int* __restrict__ morpho) {
    int b = blockIdx.x;
    int i = threadIdx.x;
    const int* mrow = morpho + b * Sn;
    __shared__ unsigned char isv[Sn];
    __shared__ int anyv;
    if (i == 0) anyv = 0;
    __syncthreads();
    int t = mrow[i];
    unsigned char iv = (t == 2);
    isv[i] = iv;
    if (iv) anyv = 1;
    g_colb[b*Sn + i] = (1.5f*0.5f) * (t == 0) + (1.2f*0.3f) * (t == 1);
    __syncthreads();
    int nearest = -1;
    if (anyv) {
        for (int d = 0; d < Sn; d++) {
            int jl = i - d;
            if (jl >= 0 && isv[jl]) { nearest = jl; break; }
            int jr = i + d;
            if (jr < Sn && isv[jr]) { nearest = jr; break; }
        }
    }
    g_vt[b*Sn + i] = nearest;
}

// ---------------- conversion kernels ----------------
__global__ void convert_split(const float* __restrict__ src,
                              __half* __restrict__ hi,
                              __half* __restrict__ lo, int n) {
    int idx = (blockIdx.x * blockDim.x + threadIdx.x) * 4;
    if (idx < n) {
        float4 x = *(const float4*)(src + idx);
        __half h0 = __float2half_rn(x.x);
        __half h1 = __float2half_rn(x.y);
        __half h2 = __float2half_rn(x.z);
        __half h3 = __float2half_rn(x.w);
        __half2 hp0, hp1, lp0, lp1;
        hp0.x = h0; hp0.y = h1; hp1.x = h2; hp1.y = h3;
        lp0.x = __float2half_rn(x.x - __half2float(h0));
        lp0.y = __float2half_rn(x.y - __half2float(h1));
        lp1.x = __float2half_rn(x.z - __half2float(h2));
        lp1.y = __float2half_rn(x.w - __half2float(h3));
        *(__half2*)(hi + idx)     = hp0;
        *(__half2*)(hi + idx + 2) = hp1;
        *(__half2*)(lo + idx)     = lp0;
        *(__half2*)(lo + idx + 2) = lp1;
    }
}

__global__ void transpose_convert_w(const float* __restrict__ Wq, const float* __restrict__ Wk,
                                    const float* __restrict__ Wv, const float* __restrict__ Wo) {
    __shared__ float t[32][33];
    int z = blockIdx.z;
    const float* W = (z == 0) ? Wq : (z == 1) ? Wk : (z == 2) ? Wv : Wo;
    __half* whi = g_wthi + (size_t)z * W_ELEMS;
    __half* wlo = g_wtlo + (size_t)z * W_ELEMS;
    int n0 = blockIdx.x * 32, k0 = blockIdx.y * 32;
    int tx = threadIdx.x, ty = threadIdx.y;
    #pragma unroll
    for (int i = 0; i < 4; i++) {
        int kr = ty + i * 8;
        t[kr][tx] = W[(size_t)(k0 + kr) * Hn + n0 + tx];
    }
    __syncthreads();
    #pragma unroll
    for (int i = 0; i < 4; i++) {
        int nr = ty + i * 8;
        float x = t[tx][nr];
        __half h = __float2half_rn(x);
        whi[(size_t)(n0 + nr) * Hn + k0 + tx] = h;
        wlo[(size_t)(n0 + nr) * Hn + k0 + tx] = __float2half_rn(x - __half2float(h));
    }
}

// ---------------- mma.sync GEMM (R7-proven loop): 2-stage cp.async, K-chunk 64 ----------------
// NPASS: 3 = AhBh+AhBl+AlBh, 2 = AhBh+AhBl (A-lo tile neither loaded nor read)
// OUTMODE: 0 = fp32 C + bias, 1 = half hi/lo, 2 = half single
#define GT_TILE 16384
#define GT_BUF  (4*GT_TILE)          // 65536 per stage (Alo slot may be unused)
#define GT_SMEM_BYTES (2*GT_BUF)     // 131072
#define NCHUNK 16

template<int NPASS, int OUTMODE>
__device__ __forceinline__ void gemm_mma_body(
    const __half* __restrict__ Ahi, const __half* __restrict__ Alo,
    const __half* __restrict__ Bhi, const __half* __restrict__ Blo,
    const float* __restrict__ bias, float* __restrict__ C,
    __half* __restrict__ Chi, __half* __restrict__ Clo)
{
    extern __shared__ char smc[];
    uint32_t smb = smem_to_u32(smc);

    int tid = threadIdx.x;
    int wid = tid >> 5, lane = tid & 31;
    int r0 = blockIdx.y * 128;
    int c0 = blockIdx.x * 128;
    int wm = (wid >> 2) * 64;
    int wn = (wid & 3) * 32;

    int la = lane & 7, qa = lane >> 3;
    int rowoff_a = (qa & 1) * 8 + la;
    int kboff_a  = (qa >> 1) * 16;
    int rowoff_b = (qa >> 1) * 8 + la;
    int kboff_b  = (qa & 1) * 16;

    float acc[4][4][4];
    #pragma unroll
    for (int mf = 0; mf < 4; mf++)
        #pragma unroll
        for (int nf = 0; nf < 4; nf++)
            #pragma unroll
            for (int j = 0; j < 4; j++) acc[mf][nf][j] = 0.f;

    auto issue_chunk = [&](uint32_t base, int kk0) {
        #pragma unroll
        for (int r = 0; r < 4; r++) {
            int idx = tid + 256 * r;
            int row = idx >> 3, c16 = idx & 7;
            uint32_t sw = swzoff(row, c16 * 16);
            size_t ga = (size_t)(r0 + row) * Hn + kk0 + c16 * 8;
            size_t gb = (size_t)(c0 + row) * Hn + kk0 + c16 * 8;
            cp_async16(base + sw,             Ahi + ga);
            if (NPASS == 3) cp_async16(base + GT_TILE + sw, Alo + ga);
            cp_async16(base + 2*GT_TILE + sw, Bhi + gb);
            cp_async16(base + 3*GT_TILE + sw, Blo + gb);
        }
        CP_COMMIT();
    };

    issue_chunk(smb, 0);

    for (int ch = 0; ch < NCHUNK; ch++) {
        if (ch + 1 < NCHUNK) {
            issue_chunk(smb + (uint32_t)((ch + 1) & 1) * GT_BUF, (ch + 1) * 64);
            CP_WAIT1();
        } else {
            CP_WAIT0();
        }
        __syncthreads();

        uint32_t cb = smb + (uint32_t)(ch & 1) * GT_BUF;
        uint32_t tAhi = cb, tAlo = cb + GT_TILE, tBhi = cb + 2*GT_TILE, tBlo = cb + 3*GT_TILE;

        #pragma unroll
        for (int ks = 0; ks < 4; ks++) {
            int kb = ks * 32;
            uint32_t Ah[4][4], Al[4][4], Bh[2][4], Bl[2][4];
            #pragma unroll
            for (int mf = 0; mf < 4; mf++) {
                int rw = wm + mf * 16 + rowoff_a;
                ldsm_x4(swz(tAhi, rw, kb + kboff_a), Ah[mf][0], Ah[mf][1], Ah[mf][2], Ah[mf][3]);
                if (NPASS == 3)
                    ldsm_x4(swz(tAlo, rw, kb + kboff_a), Al[mf][0], Al[mf][1], Al[mf][2], Al[mf][3]);
            }
            #pragma unroll
            for (int g = 0; g < 2; g++) {
                int rwb = wn + g * 16 + rowoff_b;
                ldsm_x4(swz(tBhi, rwb, kb + kboff_b), Bh[g][0], Bh[g][1], Bh[g][2], Bh[g][3]);
                ldsm_x4(swz(tBlo, rwb, kb + kboff_b), Bl[g][0], Bl[g][1], Bl[g][2], Bl[g][3]);
            }
            #pragma unroll
            for (int mf = 0; mf < 4; mf++)
                #pragma unroll
                for (int nf = 0; nf < 4; nf++)
                    mma16816(acc[mf][nf], Ah[mf][0], Ah[mf][1], Ah[mf][2], Ah[mf][3],
                             Bh[nf >> 1][(nf & 1) * 2], Bh[nf >> 1][(nf & 1) * 2 + 1]);
            #pragma unroll
            for (int mf = 0; mf < 4; mf++)
                #pragma unroll
                for (int nf = 0; nf < 4; nf++)
                    mma16816(acc[mf][nf], Ah[mf][0], Ah[mf][1], Ah[mf][2], Ah[mf][3],
                             Bl[nf >> 1][(nf & 1) * 2], Bl[nf >> 1][(nf & 1) * 2 + 1]);
            if (NPASS == 3) {
                #pragma unroll
                for (int mf = 0; mf < 4; mf++)
                    #pragma unroll
                    for (int nf = 0; nf < 4; nf++)
                        mma16816(acc[mf][nf], Al[mf][0], Al[mf][1], Al[mf][2], Al[mf][3],
                                 Bh[nf >> 1][(nf & 1) * 2], Bh[nf >> 1][(nf & 1) * 2 + 1]);
            }
        }
        __syncthreads();
    }

    #pragma unroll
    for (int mf = 0; mf < 4; mf++) {
        int row = r0 + wm + mf * 16 + (lane >> 2);
        #pragma unroll
        for (int nf = 0; nf < 4; nf++) {
            int col = c0 + wn + nf * 8 + 2 * (lane & 3);
            float b0 = bias[col], b1 = bias[col + 1];
            float v0 = acc[mf][nf][0] + b0, v1 = acc[mf][nf][1] + b1;
            float v2 = acc[mf][nf][2] + b0, v3 = acc[mf][nf][3] + b1;
            if (OUTMODE == 1) {
                __half2 h0 = __floats2half2_rn(v0, v1);
                __half2 l0 = __floats2half2_rn(v0 - __half2float(h0.x), v1 - __half2float(h0.y));
                __half2 h1 = __floats2half2_rn(v2, v3);
                __half2 l1 = __floats2half2_rn(v2 - __half2float(h1.x), v3 - __half2float(h1.y));
                *(__half2*)(Chi + (size_t)row * Hn + col)       = h0;
                *(__half2*)(Clo + (size_t)row * Hn + col)       = l0;
                *(__half2*)(Chi + (size_t)(row + 8) * Hn + col) = h1;
                *(__half2*)(Clo + (size_t)(row + 8) * Hn + col) = l1;
            } else if (OUTMODE == 2) {
                *(__half2*)(Chi + (size_t)row * Hn + col)       = __floats2half2_rn(v0, v1);
                *(__half2*)(Chi + (size_t)(row + 8) * Hn + col) = __floats2half2_rn(v2, v3);
            } else {
                *(float2*)(C + (size_t)row * Hn + col)       = make_float2(v0, v1);
                *(float2*)(C + (size_t)(row + 8) * Hn + col) = make_float2(v2, v3);
            }
        }
    }
}

__global__ void __launch_bounds__(256, 1) qkv_tc(
    const float* __restrict__ bq, const float* __restrict__ bk, const float* __restrict__ bv)
{
    int z = blockIdx.z;
    if (z == 0) {
        gemm_mma_body<3, 1>(g_xhi, g_xlo, g_wthi, g_wtlo, bq, nullptr, g_qhi, g_qlo);
    } else if (z == 1) {
        gemm_mma_body<3, 1>(g_xhi, g_xlo, g_wthi + W_ELEMS, g_wtlo + W_ELEMS, bk,
                            nullptr, g_khi, g_klo);
    } else {
        // V: 2-pass (logit-free path), single-fp16 output
        gemm_mma_body<2, 2>(g_xhi, nullptr, g_wthi + 2*(size_t)W_ELEMS,
                            g_wtlo + 2*(size_t)W_ELEMS, bv, nullptr, g_v1, nullptr);
    }
}

__global__ void __launch_bounds__(256, 1) out_tc(const float* __restrict__ bo, float* __restrict__ C)
{
    // O single fp16, W hi/lo: 2-pass exact in W
    gemm_mma_body<2, 0>(g_o1, nullptr, g_wthi + 3*(size_t)W_ELEMS,
                        g_wtlo + 3*(size_t)W_ELEMS, bo, C, nullptr, nullptr);
}

// ---------------- flash attention on mma.sync (R10 structure, V single fp16) ----------------
// CTA: 128 q-rows x (b,h), 256 threads / 8 warps. KV stage = Kh(8K)+Kl(8K)+V(8K) = 24KB.
#define AT_KVBUF 24576
#define AT_SMEM (4096 + 2*AT_KVBUF)  // 53248

__device__ __forceinline__ void qk6(float* c0, float* c1, uint32_t* Q4a, uint32_t* Q4b,
                                    uint32_t* kh, uint32_t* kl) {
    mma16816(c0, Q4a[0], Q4a[1], Q4a[2], Q4a[3], kh[0], kh[1]);
    mma16816(c1, Q4a[0], Q4a[1], Q4a[2], Q4a[3], kh[2], kh[3]);
    mma16816(c0, Q4a[0], Q4a[1], Q4a[2], Q4a[3], kl[0], kl[1]);
    mma16816(c1, Q4a[0], Q4a[1], Q4a[2], Q4a[3], kl[2], kl[3]);
    mma16816(c0, Q4b[0], Q4b[1], Q4b[2], Q4b[3], kh[0], kh[1]);
    mma16816(c1, Q4b[0], Q4b[1], Q4b[2], Q4b[3], kh[2], kh[3]);
}

__global__ void __launch_bounds__(256) attn_mma() {
    extern __shared__ char smc[];
    uint32_t smb = smem_to_u32(smc);
    float* colb_sm = (float*)smc;
    uint32_t bufb = smb + 4096;

    int tid = threadIdx.x;
    int wid = tid >> 5, lane = tid & 31;
    int b = blockIdx.z, h = blockIdx.y;
    int i0 = blockIdx.x * 128;

    int la = lane & 7, qa = lane >> 3;
    int roa = (qa & 1) * 8 + la, kba = (qa >> 1) * 16;   // A-style / trans-V style
    int rob = (qa >> 1) * 8 + la, kbb = (qa & 1) * 16;   // B-style (K)

    // stage colb pre-scaled by log2e
    #pragma unroll
    for (int r = 0; r < 4; r++)
        colb_sm[tid + 256 * r] = g_colb[b * Sn + tid + 256 * r] * LOG2E;

    // stage Q tile [128 x 64] hi/lo into buffer region, extract to regs
    {
        const __half* qhb = g_qhi + (size_t)(b * Sn + i0) * Hn + h * HDn;
        const __half* qlb = g_qlo + (size_t)(b * Sn + i0) * Hn + h * HDn;
        #pragma unroll
        for (int r = 0; r < 4; r++) {
            int idx = tid + 256 * r;
            int row = idx >> 3, c16 = idx & 7;
            uint32_t sw = swzoff(row, c16 * 16);
            size_t ga = (size_t)row * Hn + c16 * 8;
            *(uint4*)(smc + 4096 + sw)         = *(const uint4*)(qhb + ga);
            *(uint4*)(smc + 4096 + 16384 + sw) = *(const uint4*)(qlb + ga);
        }
    }
    __syncthreads();
    uint32_t Qh[4][4], Ql[4][4];
    #pragma unroll
    for (int kd = 0; kd < 4; kd++) {
        int rw = wid * 16 + roa;
        ldsm_x4(swz(bufb, rw, kd * 32 + kba),         Qh[kd][0], Qh[kd][1], Qh[kd][2], Qh[kd][3]);
        ldsm_x4(swz(bufb + 16384, rw, kd * 32 + kba), Ql[kd][0], Ql[kd][1], Ql[kd][2], Ql[kd][3]);
    }
    __syncthreads();   // ldmatrix done before cp.async overwrites region

    int r_g = i0 + wid * 16 + (lane >> 2);
    int vt0 = g_vt[b * Sn + r_g];
    int vt1 = g_vt[b * Sn + r_g + 8];

    float m0 = -3.0e38f, m1 = -3.0e38f, l0 = 0.f, l1 = 0.f;
    float acc[8][4];
    #pragma unroll
    for (int t = 0; t < 8; t++)
        #pragma unroll
        for (int j = 0; j < 4; j++) acc[t][j] = 0.f;

    const __half* khb = g_khi + (size_t)b * Sn * Hn + h * HDn;
    const __half* klb = g_klo + (size_t)b * Sn * Hn + h * HDn;
    const __half* vb  = g_v1  + (size_t)b * Sn * Hn + h * HDn;

    auto issue_kv = [&](uint32_t base, int j0) {
        #pragma unroll
        for (int r = 0; r < 2; r++) {
            int idx = tid + 256 * r;
            int row = idx >> 3, c16 = idx & 7;
            uint32_t sw = swzoff(row, c16 * 16);
            size_t go = (size_t)(j0 + row) * Hn + c16 * 8;
            cp_async16(base + sw,         khb + go);
            cp_async16(base + 8192 + sw,  klb + go);
            cp_async16(base + 16384 + sw, vb + go);
        }
        CP_COMMIT();
    };

    issue_kv(bufb, 0);

    for (int jt = 0; jt < Sn / 64; jt++) {
        if (jt + 1 < Sn / 64) {
            issue_kv(bufb + ((jt + 1) & 1) * AT_KVBUF, (jt + 1) * 64);
            CP_WAIT1();
        } else {
            CP_WAIT0();
        }
        __syncthreads();

        uint32_t cb = bufb + (jt & 1) * AT_KVBUF;
        uint32_t Kh = cb, Kl = cb + 8192, Vt = cb + 16384;

        // S = Q K^T (3-pass hi/lo, fp16)
        float s[8][4];
        #pragma unroll
        for (int t = 0; t < 8; t++)
            #pragma unroll
            for (int j = 0; j < 4; j++) s[t][j] = 0.f;
        #pragma unroll
        for (int kd = 0; kd < 4; kd++) {
            #pragma unroll
            for (int ng = 0; ng < 4; ng++) {
                uint32_t kh[4], kl[4];
                ldsm_x4(swz(Kh, ng * 16 + rob, kd * 32 + kbb), kh[0], kh[1], kh[2], kh[3]);
                ldsm_x4(swz(Kl, ng * 16 + rob, kd * 32 + kbb), kl[0], kl[1], kl[2], kl[3]);
                qk6(s[2*ng], s[2*ng+1], Qh[kd], Ql[kd], kh, kl);
            }
        }

        // scale + bias (log2 domain) + online softmax
        float rmax0 = -3.0e38f, rmax1 = -3.0e38f;
        #pragma unroll
        for (int t = 0; t < 8; t++) {
            int jc = jt * 64 + t * 8 + (lane & 3) * 2;
            float cb0 = colb_sm[jc], cb1 = colb_sm[jc + 1];
            s[t][0] = s[t][0] * SCALE_L2E + cb0 + (jc     == vt0 ? VERB_L2E : 0.f);
            s[t][1] = s[t][1] * SCALE_L2E + cb1 + (jc + 1 == vt0 ? VERB_L2E : 0.f);
            s[t][2] = s[t][2] * SCALE_L2E + cb0 + (jc     == vt1 ? VERB_L2E : 0.f);
            s[t][3] = s[t][3] * SCALE_L2E + cb1 + (jc + 1 == vt1 ? VERB_L2E : 0.f);
            rmax0 = fmaxf(rmax0, fmaxf(s[t][0], s[t][1]));
            rmax1 = fmaxf(rmax1, fmaxf(s[t][2], s[t][3]));
        }
        rmax0 = fmaxf(rmax0, __shfl_xor_sync(0xffffffffu, rmax0, 1));
        rmax0 = fmaxf(rmax0, __shfl_xor_sync(0xffffffffu, rmax0, 2));
        rmax1 = fmaxf(rmax1, __shfl_xor_sync(0xffffffffu, rmax1, 1));
        rmax1 = fmaxf(rmax1, __shfl_xor_sync(0xffffffffu, rmax1, 2));
        float mn0 = fmaxf(m0, rmax0), mn1 = fmaxf(m1, rmax1);
        float cr0 = ex2f(m0 - mn0), cr1 = ex2f(m1 - mn1);
        m0 = mn0; m1 = mn1;

        float sum0 = 0.f, sum1 = 0.f;
        uint32_t Ph[4][4], Pl[4][4];
        #pragma unroll
        for (int g = 0; g < 4; g++) {
            #pragma unroll
            for (int hh = 0; hh < 2; hh++) {
                int t = 2 * g + hh;
                float p0 = ex2f(s[t][0] - mn0);
                float p1 = ex2f(s[t][1] - mn0);
                float p2 = ex2f(s[t][2] - mn1);
                float p3 = ex2f(s[t][3] - mn1);
                sum0 += p0 + p1; sum1 += p2 + p3;
                uint32_t h01 = pack_f16(p0, p1);
                uint32_t h23 = pack_f16(p2, p3);
                __half2 hh01 = *(__half2*)&h01;
                __half2 hh23 = *(__half2*)&h23;
                uint32_t l01 = pack_f16(p0 - __half2float(hh01.x), p1 - __half2float(hh01.y));
                uint32_t l23 = pack_f16(p2 - __half2float(hh23.x), p3 - __half2float(hh23.y));
                Ph[g][hh * 2]     = h01;
                Ph[g][hh * 2 + 1] = h23;
                Pl[g][hh * 2]     = l01;
                Pl[g][hh * 2 + 1] = l23;
            }
        }
        sum0 += __shfl_xor_sync(0xffffffffu, sum0, 1);
        sum0 += __shfl_xor_sync(0xffffffffu, sum0, 2);
        sum1 += __shfl_xor_sync(0xffffffffu, sum1, 1);
        sum1 += __shfl_xor_sync(0xffffffffu, sum1, 2);
        l0 = l0 * cr0 + sum0;
        l1 = l1 * cr1 + sum1;
        #pragma unroll
        for (int t = 0; t < 8; t++) {
            acc[t][0] *= cr0; acc[t][1] *= cr0;
            acc[t][2] *= cr1; acc[t][3] *= cr1;
        }

        // O += P V  (P hi/lo exact, V single fp16): 4 MMAs per (g,gd)
        #pragma unroll
        for (int g = 0; g < 4; g++) {
            #pragma unroll
            for (int gd = 0; gd < 4; gd++) {
                uint32_t vh[4];
                ldsm_x4_t(swz(Vt, g * 16 + roa, gd * 32 + kba), vh[0], vh[1], vh[2], vh[3]);
                float* c0 = acc[2*gd];
                float* c1 = acc[2*gd+1];
                mma16816(c0, Ph[g][0], Ph[g][1], Ph[g][2], Ph[g][3], vh[0], vh[1]);
                mma16816(c1, Ph[g][0], Ph[g][1], Ph[g][2], Ph[g][3], vh[2], vh[3]);
                mma16816(c0, Pl[g][0], Pl[g][1], Pl[g][2], Pl[g][3], vh[0], vh[1]);
                mma16816(c1, Pl[g][0], Pl[g][1], Pl[g][2], Pl[g][3], vh[2], vh[3]);
            }
        }
        __syncthreads();
    }

    // epilogue: normalize, store single fp16
    float inv0 = 1.f / l0, inv1 = 1.f / l1;
    __half* ob = g_o1 + (size_t)(b * Sn + r_g) * Hn + h * HDn;
    #pragma unroll
    for (int t = 0; t < 8; t++) {
        int d = t * 8 + (lane & 3) * 2;
        *(__half2*)(ob + d) =
            __floats2half2_rn(acc[t][0] * inv0, acc[t][1] * inv0);
        *(__half2*)(ob + (size_t)8 * Hn + d) =
            __floats2half2_rn(acc[t][2] * inv1, acc[t][3] * inv1);
    }
}

// ---------------- launch ----------------
extern "C" void kernel_launch(void* const* d_in, const int* in_sizes, int n_in,
                              void* d_out, int out_size) {
    const float* hidden = (const float*)d_in[0];
    const int*   morpho = (const int*)d_in[1];
    const float* Wq = (const float*)d_in[2];
    const float* bq = (const float*)d_in[3];
    const float* Wk = (const float*)d_in[4];
    const float* bk = (const float*)d_in[5];
    const float* Wv = (const float*)d_in[6];
    const float* bv = (const float*)d_in[7];
    const float* Wo = (const float*)d_in[8];
    const float* bo = (const float*)d_in[9];
    float* out = (float*)d_out;

    cudaFuncSetAttribute(qkv_tc,
                         cudaFuncAttributeMaxDynamicSharedMemorySize, GT_SMEM_BYTES);
    cudaFuncSetAttribute(out_tc,
                         cudaFuncAttributeMaxDynamicSharedMemorySize, GT_SMEM_BYTES);
    cudaFuncSetAttribute(attn_mma,
                         cudaFuncAttributeMaxDynamicSharedMemorySize, AT_SMEM);

    static __half *xhi_p = nullptr, *xlo_p = nullptr;
    if (!xhi_p) {
        cudaGetSymbolAddress((void**)&xhi_p, g_xhi);
        cudaGetSymbolAddress((void**)&xlo_p, g_xlo);
    }

    morpho_kernel<<<Bn, Sn>>>(morpho);
    convert_split<<<(Mtot*Hn/4 + 255) / 256, 256>>>(hidden, xhi_p, xlo_p, Mtot*Hn);
    transpose_convert_w<<<dim3(32, 32, 4), dim3(32, 8)>>>(Wq, Wk, Wv, Wo);
    qkv_tc<<<dim3(Hn/128, Mtot/128, 3), 256, GT_SMEM_BYTES>>>(bq, bk, bv);
    attn_mma<<<dim3(Sn/128, NHn, Bn), 256, AT_SMEM>>>();
    out_tc<<<dim3(Hn/128, Mtot/128, 1), 256, GT_SMEM_BYTES>>>(bo, out);
}

// round 14
// speedup vs baseline: 2.1642x; 1.2299x over previous
#include <cuda_runtime.h>
#include <cuda_fp16.h>
#include <cstdint>

#define Bn 4
#define Sn 1024
#define Hn 1024
#define NHn 16
#define HDn 64
#define LOG2E 1.4426950408889634f
#define SCALE_L2E (0.125f * 1.4426950408889634f)
#define VERB_L2E (2.0f * 1.4426950408889634f)

#define Mtot (Bn*Sn)     // 4096
#define W_ELEMS (Hn*Hn)  // 1048576

// ---------------- scratch (allocation-free) ----------------
__device__ float g_colb[Bn*Sn];
__device__ int   g_vt[Bn*Sn];

__device__ __half g_xh [Mtot*Hn];     // hidden, single fp16
__device__ __half g_q1 [Mtot*Hn];     // Q single fp16
__device__ __half g_k1 [Mtot*Hn];     // K single fp16
__device__ __half g_v1 [Mtot*Hn];     // V single fp16
__device__ __half g_o1 [Mtot*Hn];     // attention output single fp16
__device__ __half g_wthi[4*W_ELEMS];  // W^T per matrix: [n][k]
__device__ __half g_wtlo[4*W_ELEMS];

// ---------------- PTX helpers (family-portable only) ----------------
__device__ __forceinline__ uint32_t smem_to_u32(const void* p) {
    uint32_t a;
    asm("{ .reg .u64 t; cvta.to.shared.u64 t, %1; cvt.u32.u64 %0, t; }" : "=r"(a) : "l"(p));
    return a;
}
__device__ __forceinline__ void ldsm_x4(uint32_t addr, uint32_t& r0, uint32_t& r1,
                                        uint32_t& r2, uint32_t& r3) {
    asm volatile("ldmatrix.sync.aligned.m8n8.x4.shared.b16 {%0,%1,%2,%3}, [%4];"
        : "=r"(r0), "=r"(r1), "=r"(r2), "=r"(r3) : "r"(addr));
}
__device__ __forceinline__ void ldsm_x4_t(uint32_t addr, uint32_t& r0, uint32_t& r1,
                                          uint32_t& r2, uint32_t& r3) {
    asm volatile("ldmatrix.sync.aligned.m8n8.x4.trans.shared.b16 {%0,%1,%2,%3}, [%4];"
        : "=r"(r0), "=r"(r1), "=r"(r2), "=r"(r3) : "r"(addr));
}
__device__ __forceinline__ void mma16816(float* c, uint32_t a0, uint32_t a1,
                                         uint32_t a2, uint32_t a3,
                                         uint32_t b0, uint32_t b1) {
    asm volatile(
        "mma.sync.aligned.m16n8k16.row.col.f32.f16.f16.f32 "
        "{%0,%1,%2,%3}, {%4,%5,%6,%7}, {%8,%9}, {%0,%1,%2,%3};"
        : "+f"(c[0]), "+f"(c[1]), "+f"(c[2]), "+f"(c[3])
        : "r"(a0), "r"(a1), "r"(a2), "r"(a3), "r"(b0), "r"(b1));
}
__device__ __forceinline__ void cp_async16(uint32_t saddr, const void* gptr) {
    asm volatile("cp.async.cg.shared.global [%0], [%1], 16;" :: "r"(saddr), "l"(gptr));
}
#define CP_COMMIT() asm volatile("cp.async.commit_group;")
#define CP_WAIT0()  asm volatile("cp.async.wait_group 0;")
#define CP_WAIT1()  asm volatile("cp.async.wait_group 1;")

__device__ __forceinline__ float ex2f(float x) {
    float y;
    asm("ex2.approx.ftz.f32 %0, %1;" : "=f"(y) : "f"(x));
    return y;
}

// SW128 swizzled address within a tile of 128B rows
__device__ __forceinline__ uint32_t swz(uint32_t base, int row, int kb) {
    uint32_t bo = (uint32_t)(row * 128 + kb);
    return base + (bo ^ ((bo >> 3) & 0x70));
}
__device__ __forceinline__ uint32_t swzoff(int row, int kb) {
    uint32_t bo = (uint32_t)(row * 128 + kb);
    return bo ^ ((bo >> 3) & 0x70);
}
__device__ __forceinline__ uint32_t pack_f16(float a, float b) {
    __half2 h = __floats2half2_rn(a, b);
    return *(uint32_t*)&h;
}

// ---------------- morpho preprocessing ----------------
__global__ void morpho_kernel(const int* __restrict__ morpho) {
    int b = blockIdx.x;
    int i = threadIdx.x;
    const int* mrow = morpho + b * Sn;
    __shared__ unsigned char isv[Sn];
    __shared__ int anyv;
    if (i == 0) anyv = 0;
    __syncthreads();
    int t = mrow[i];
    unsigned char iv = (t == 2);
    isv[i] = iv;
    if (iv) anyv = 1;
    g_colb[b*Sn + i] = (1.5f*0.5f) * (t == 0) + (1.2f*0.3f) * (t == 1);
    __syncthreads();
    int nearest = -1;
    if (anyv) {
        for (int d = 0; d < Sn; d++) {
            int jl = i - d;
            if (jl >= 0 && isv[jl]) { nearest = jl; break; }
            int jr = i + d;
            if (jr < Sn && isv[jr]) { nearest = jr; break; }
        }
    }
    g_vt[b*Sn + i] = nearest;
}

// ---------------- conversion kernels ----------------
__global__ void convert_half(const float* __restrict__ src,
                             __half* __restrict__ hi, int n) {
    int idx = (blockIdx.x * blockDim.x + threadIdx.x) * 4;
    if (idx < n) {
        float4 x = *(const float4*)(src + idx);
        *(__half2*)(hi + idx)     = __floats2half2_rn(x.x, x.y);
        *(__half2*)(hi + idx + 2) = __floats2half2_rn(x.z, x.w);
    }
}

__global__ void transpose_convert_w(const float* __restrict__ Wq, const float* __restrict__ Wk,
                                    const float* __restrict__ Wv, const float* __restrict__ Wo) {
    __shared__ float t[32][33];
    int z = blockIdx.z;
    const float* W = (z == 0) ? Wq : (z == 1) ? Wk : (z == 2) ? Wv : Wo;
    __half* whi = g_wthi + (size_t)z * W_ELEMS;
    __half* wlo = g_wtlo + (size_t)z * W_ELEMS;
    int n0 = blockIdx.x * 32, k0 = blockIdx.y * 32;
    int tx = threadIdx.x, ty = threadIdx.y;
    #pragma unroll
    for (int i = 0; i < 4; i++) {
        int kr = ty + i * 8;
        t[kr][tx] = W[(size_t)(k0 + kr) * Hn + n0 + tx];
    }
    __syncthreads();
    #pragma unroll
    for (int i = 0; i < 4; i++) {
        int nr = ty + i * 8;
        float x = t[tx][nr];
        __half h = __float2half_rn(x);
        whi[(size_t)(n0 + nr) * Hn + k0 + tx] = h;
        wlo[(size_t)(n0 + nr) * Hn + k0 + tx] = __float2half_rn(x - __half2float(h));
    }
}

// ---------------- mma.sync GEMM: 2-pass (Ah·Bh + Ah·Bl), 2-stage cp.async ----------------
// Stage = A(16K) + Bhi(16K) + Blo(16K) = 48KB; 2 stages = 96KB.
// OUTMODE: 0 = fp32 C + bias, 2 = half single
#define GT_TILE 16384
#define GT_BUF  (3*GT_TILE)          // 49152 per stage
#define GT_SMEM_BYTES (2*GT_BUF)     // 98304
#define NCHUNK 16

template<int OUTMODE>
__device__ __forceinline__ void gemm_mma_body(
    const __half* __restrict__ A,
    const __half* __restrict__ Bhi, const __half* __restrict__ Blo,
    const float* __restrict__ bias, float* __restrict__ C,
    __half* __restrict__ Ch)
{
    extern __shared__ char smc[];
    uint32_t smb = smem_to_u32(smc);

    int tid = threadIdx.x;
    int wid = tid >> 5, lane = tid & 31;
    int r0 = blockIdx.y * 128;
    int c0 = blockIdx.x * 128;
    int wm = (wid >> 2) * 64;
    int wn = (wid & 3) * 32;

    int la = lane & 7, qa = lane >> 3;
    int rowoff_a = (qa & 1) * 8 + la;
    int kboff_a  = (qa >> 1) * 16;
    int rowoff_b = (qa >> 1) * 8 + la;
    int kboff_b  = (qa & 1) * 16;

    float acc[4][4][4];
    #pragma unroll
    for (int mf = 0; mf < 4; mf++)
        #pragma unroll
        for (int nf = 0; nf < 4; nf++)
            #pragma unroll
            for (int j = 0; j < 4; j++) acc[mf][nf][j] = 0.f;

    auto issue_chunk = [&](uint32_t base, int kk0) {
        #pragma unroll
        for (int r = 0; r < 4; r++) {
            int idx = tid + 256 * r;
            int row = idx >> 3, c16 = idx & 7;
            uint32_t sw = swzoff(row, c16 * 16);
            size_t ga = (size_t)(r0 + row) * Hn + kk0 + c16 * 8;
            size_t gb = (size_t)(c0 + row) * Hn + kk0 + c16 * 8;
            cp_async16(base + sw,             A + ga);
            cp_async16(base + GT_TILE + sw,   Bhi + gb);
            cp_async16(base + 2*GT_TILE + sw, Blo + gb);
        }
        CP_COMMIT();
    };

    issue_chunk(smb, 0);

    for (int ch = 0; ch < NCHUNK; ch++) {
        if (ch + 1 < NCHUNK) {
            issue_chunk(smb + (uint32_t)((ch + 1) & 1) * GT_BUF, (ch + 1) * 64);
            CP_WAIT1();
        } else {
            CP_WAIT0();
        }
        __syncthreads();

        uint32_t cb = smb + (uint32_t)(ch & 1) * GT_BUF;
        uint32_t tA = cb, tBhi = cb + GT_TILE, tBlo = cb + 2*GT_TILE;

        #pragma unroll
        for (int ks = 0; ks < 4; ks++) {
            int kb = ks * 32;
            uint32_t Ar[4][4], Bh[2][4], Bl[2][4];
            #pragma unroll
            for (int mf = 0; mf < 4; mf++) {
                int rw = wm + mf * 16 + rowoff_a;
                ldsm_x4(swz(tA, rw, kb + kboff_a), Ar[mf][0], Ar[mf][1], Ar[mf][2], Ar[mf][3]);
            }
            #pragma unroll
            for (int g = 0; g < 2; g++) {
                int rwb = wn + g * 16 + rowoff_b;
                ldsm_x4(swz(tBhi, rwb, kb + kboff_b), Bh[g][0], Bh[g][1], Bh[g][2], Bh[g][3]);
                ldsm_x4(swz(tBlo, rwb, kb + kboff_b), Bl[g][0], Bl[g][1], Bl[g][2], Bl[g][3]);
            }
            #pragma unroll
            for (int mf = 0; mf < 4; mf++)
                #pragma unroll
                for (int nf = 0; nf < 4; nf++)
                    mma16816(acc[mf][nf], Ar[mf][0], Ar[mf][1], Ar[mf][2], Ar[mf][3],
                             Bh[nf >> 1][(nf & 1) * 2], Bh[nf >> 1][(nf & 1) * 2 + 1]);
            #pragma unroll
            for (int mf = 0; mf < 4; mf++)
                #pragma unroll
                for (int nf = 0; nf < 4; nf++)
                    mma16816(acc[mf][nf], Ar[mf][0], Ar[mf][1], Ar[mf][2], Ar[mf][3],
                             Bl[nf >> 1][(nf & 1) * 2], Bl[nf >> 1][(nf & 1) * 2 + 1]);
        }
        __syncthreads();
    }

    #pragma unroll
    for (int mf = 0; mf < 4; mf++) {
        int row = r0 + wm + mf * 16 + (lane >> 2);
        #pragma unroll
        for (int nf = 0; nf < 4; nf++) {
            int col = c0 + wn + nf * 8 + 2 * (lane & 3);
            float b0 = bias[col], b1 = bias[col + 1];
            float v0 = acc[mf][nf][0] + b0, v1 = acc[mf][nf][1] + b1;
            float v2 = acc[mf][nf][2] + b0, v3 = acc[mf][nf][3] + b1;
            if (OUTMODE == 2) {
                *(__half2*)(Ch + (size_t)row * Hn + col)       = __floats2half2_rn(v0, v1);
                *(__half2*)(Ch + (size_t)(row + 8) * Hn + col) = __floats2half2_rn(v2, v3);
            } else {
                *(float2*)(C + (size_t)row * Hn + col)       = make_float2(v0, v1);
                *(float2*)(C + (size_t)(row + 8) * Hn + col) = make_float2(v2, v3);
            }
        }
    }
}

__global__ void __launch_bounds__(256, 1) qkv_tc(
    const float* __restrict__ bq, const float* __restrict__ bk, const float* __restrict__ bv)
{
    int z = blockIdx.z;
    const float* bias = (z == 0) ? bq : (z == 1) ? bk : bv;
    __half* Ch = (z == 0) ? g_q1 : (z == 1) ? g_k1 : g_v1;
    gemm_mma_body<2>(g_xh, g_wthi + (size_t)z * W_ELEMS, g_wtlo + (size_t)z * W_ELEMS,
                     bias, nullptr, Ch);
}

__global__ void __launch_bounds__(256, 1) out_tc(const float* __restrict__ bo, float* __restrict__ C)
{
    gemm_mma_body<0>(g_o1, g_wthi + 3*(size_t)W_ELEMS, g_wtlo + 3*(size_t)W_ELEMS,
                     bo, C, nullptr);
}

// ---------------- flash attention: Q,K,V single fp16; QK 1-pass; PV (Ph+Pl)·V ----------------
// CTA: 128 q-rows x (b,h), 256 threads / 8 warps. KV stage = K(8K)+V(8K) = 16KB.
#define AT_KVBUF 16384
#define AT_SMEM (4096 + 2*AT_KVBUF)  // 36864

__global__ void __launch_bounds__(256) attn_mma() {
    extern __shared__ char smc[];
    uint32_t smb = smem_to_u32(smc);
    float* colb_sm = (float*)smc;
    uint32_t bufb = smb + 4096;

    int tid = threadIdx.x;
    int wid = tid >> 5, lane = tid & 31;
    int b = blockIdx.z, h = blockIdx.y;
    int i0 = blockIdx.x * 128;

    int la = lane & 7, qa = lane >> 3;
    int roa = (qa & 1) * 8 + la, kba = (qa >> 1) * 16;   // A-style / trans-V style
    int rob = (qa >> 1) * 8 + la, kbb = (qa & 1) * 16;   // B-style (K)

    // stage colb pre-scaled by log2e
    #pragma unroll
    for (int r = 0; r < 4; r++)
        colb_sm[tid + 256 * r] = g_colb[b * Sn + tid + 256 * r] * LOG2E;

    // stage Q tile [128 x 64] into buffer region, extract to regs
    {
        const __half* qb = g_q1 + (size_t)(b * Sn + i0) * Hn + h * HDn;
        #pragma unroll
        for (int r = 0; r < 4; r++) {
            int idx = tid + 256 * r;
            int row = idx >> 3, c16 = idx & 7;
            uint32_t sw = swzoff(row, c16 * 16);
            *(uint4*)(smc + 4096 + sw) = *(const uint4*)(qb + (size_t)row * Hn + c16 * 8);
        }
    }
    __syncthreads();
    uint32_t Qh[4][4];
    #pragma unroll
    for (int kd = 0; kd < 4; kd++) {
        int rw = wid * 16 + roa;
        ldsm_x4(swz(bufb, rw, kd * 32 + kba), Qh[kd][0], Qh[kd][1], Qh[kd][2], Qh[kd][3]);
    }
    __syncthreads();   // ldmatrix done before cp.async overwrites region

    int r_g = i0 + wid * 16 + (lane >> 2);
    int vt0 = g_vt[b * Sn + r_g];
    int vt1 = g_vt[b * Sn + r_g + 8];

    float m0 = -3.0e38f, m1 = -3.0e38f, l0 = 0.f, l1 = 0.f;
    float acc[8][4];
    #pragma unroll
    for (int t = 0; t < 8; t++)
        #pragma unroll
        for (int j = 0; j < 4; j++) acc[t][j] = 0.f;

    const __half* kb0 = g_k1 + (size_t)b * Sn * Hn + h * HDn;
    const __half* vb0 = g_v1 + (size_t)b * Sn * Hn + h * HDn;

    auto issue_kv = [&](uint32_t base, int j0) {
        #pragma unroll
        for (int r = 0; r < 2; r++) {
            int idx = tid + 256 * r;
            int row = idx >> 3, c16 = idx & 7;
            uint32_t sw = swzoff(row, c16 * 16);
            size_t go = (size_t)(j0 + row) * Hn + c16 * 8;
            cp_async16(base + sw,        kb0 + go);
            cp_async16(base + 8192 + sw, vb0 + go);
        }
        CP_COMMIT();
    };

    issue_kv(bufb, 0);

    for (int jt = 0; jt < Sn / 64; jt++) {
        if (jt + 1 < Sn / 64) {
            issue_kv(bufb + ((jt + 1) & 1) * AT_KVBUF, (jt + 1) * 64);
            CP_WAIT1();
        } else {
            CP_WAIT0();
        }
        __syncthreads();

        uint32_t cb = bufb + (jt & 1) * AT_KVBUF;
        uint32_t Kt = cb, Vt = cb + 8192;

        // S = Q K^T (1 pass, single fp16)
        float s[8][4];
        #pragma unroll
        for (int t = 0; t < 8; t++)
            #pragma unroll
            for (int j = 0; j < 4; j++) s[t][j] = 0.f;
        #pragma unroll
        for (int kd = 0; kd < 4; kd++) {
            #pragma unroll
            for (int ng = 0; ng < 4; ng++) {
                uint32_t kh[4];
                ldsm_x4(swz(Kt, ng * 16 + rob, kd * 32 + kbb), kh[0], kh[1], kh[2], kh[3]);
                mma16816(s[2*ng],   Qh[kd][0], Qh[kd][1], Qh[kd][2], Qh[kd][3], kh[0], kh[1]);
                mma16816(s[2*ng+1], Qh[kd][0], Qh[kd][1], Qh[kd][2], Qh[kd][3], kh[2], kh[3]);
            }
        }

        // scale + bias (log2 domain) + online softmax
        float rmax0 = -3.0e38f, rmax1 = -3.0e38f;
        #pragma unroll
        for (int t = 0; t < 8; t++) {
            int jc = jt * 64 + t * 8 + (lane & 3) * 2;
            float cb0 = colb_sm[jc], cb1 = colb_sm[jc + 1];
            s[t][0] = s[t][0] * SCALE_L2E + cb0 + (jc     == vt0 ? VERB_L2E : 0.f);
            s[t][1] = s[t][1] * SCALE_L2E + cb1 + (jc + 1 == vt0 ? VERB_L2E : 0.f);
            s[t][2] = s[t][2] * SCALE_L2E + cb0 + (jc     == vt1 ? VERB_L2E : 0.f);
            s[t][3] = s[t][3] * SCALE_L2E + cb1 + (jc + 1 == vt1 ? VERB_L2E : 0.f);
            rmax0 = fmaxf(rmax0, fmaxf(s[t][0], s[t][1]));
            rmax1 = fmaxf(rmax1, fmaxf(s[t][2], s[t][3]));
        }
        rmax0 = fmaxf(rmax0, __shfl_xor_sync(0xffffffffu, rmax0, 1));
        rmax0 = fmaxf(rmax0, __shfl_xor_sync(0xffffffffu, rmax0, 2));
        rmax1 = fmaxf(rmax1, __shfl_xor_sync(0xffffffffu, rmax1, 1));
        rmax1 = fmaxf(rmax1, __shfl_xor_sync(0xffffffffu, rmax1, 2));
        float mn0 = fmaxf(m0, rmax0), mn1 = fmaxf(m1, rmax1);
        float cr0 = ex2f(m0 - mn0), cr1 = ex2f(m1 - mn1);
        m0 = mn0; m1 = mn1;

        float sum0 = 0.f, sum1 = 0.f;
        uint32_t Ph[4][4], Pl[4][4];
        #pragma unroll
        for (int g = 0; g < 4; g++) {
            #pragma unroll
            for (int hh = 0; hh < 2; hh++) {
                int t = 2 * g + hh;
                float p0 = ex2f(s[t][0] - mn0);
                float p1 = ex2f(s[t][1] - mn0);
                float p2 = ex2f(s[t][2] - mn1);
                float p3 = ex2f(s[t][3] - mn1);
                sum0 += p0 + p1; sum1 += p2 + p3;
                uint32_t h01 = pack_f16(p0, p1);
                uint32_t h23 = pack_f16(p2, p3);
                __half2 hh01 = *(__half2*)&h01;
                __half2 hh23 = *(__half2*)&h23;
                uint32_t l01 = pack_f16(p0 - __half2float(hh01.x), p1 - __half2float(hh01.y));
                uint32_t l23 = pack_f16(p2 - __half2float(hh23.x), p3 - __half2float(hh23.y));
                Ph[g][hh * 2]     = h01;
                Ph[g][hh * 2 + 1] = h23;
                Pl[g][hh * 2]     = l01;
                Pl[g][hh * 2 + 1] = l23;
            }
        }
        sum0 += __shfl_xor_sync(0xffffffffu, sum0, 1);
        sum0 += __shfl_xor_sync(0xffffffffu, sum0, 2);
        sum1 += __shfl_xor_sync(0xffffffffu, sum1, 1);
        sum1 += __shfl_xor_sync(0xffffffffu, sum1, 2);
        l0 = l0 * cr0 + sum0;
        l1 = l1 * cr1 + sum1;
        #pragma unroll
        for (int t = 0; t < 8; t++) {
            acc[t][0] *= cr0; acc[t][1] *= cr0;
            acc[t][2] *= cr1; acc[t][3] *= cr1;
        }

        // O += P V  (P hi/lo exact, V single fp16): 4 MMAs per (g,gd)
        #pragma unroll
        for (int g = 0; g < 4; g++) {
            #pragma unroll
            for (int gd = 0; gd < 4; gd++) {
                uint32_t vh[4];
                ldsm_x4_t(swz(Vt, g * 16 + roa, gd * 32 + kba), vh[0], vh[1], vh[2], vh[3]);
                float* c0 = acc[2*gd];
                float* c1 = acc[2*gd+1];
                mma16816(c0, Ph[g][0], Ph[g][1], Ph[g][2], Ph[g][3], vh[0], vh[1]);
                mma16816(c1, Ph[g][0], Ph[g][1], Ph[g][2], Ph[g][3], vh[2], vh[3]);
                mma16816(c0, Pl[g][0], Pl[g][1], Pl[g][2], Pl[g][3], vh[0], vh[1]);
                mma16816(c1, Pl[g][0], Pl[g][1], Pl[g][2], Pl[g][3], vh[2], vh[3]);
            }
        }
        __syncthreads();
    }

    // epilogue: normalize, store single fp16
    float inv0 = 1.f / l0, inv1 = 1.f / l1;
    __half* ob = g_o1 + (size_t)(b * Sn + r_g) * Hn + h * HDn;
    #pragma unroll
    for (int t = 0; t < 8; t++) {
        int d = t * 8 + (lane & 3) * 2;
        *(__half2*)(ob + d) =
            __floats2half2_rn(acc[t][0] * inv0, acc[t][1] * inv0);
        *(__half2*)(ob + (size_t)8 * Hn + d) =
            __floats2half2_rn(acc[t][2] * inv1, acc[t][3] * inv1);
    }
}

// ---------------- launch ----------------
extern "C" void kernel_launch(void* const* d_in, const int* in_sizes, int n_in,
                              void* d_out, int out_size) {
    const float* hidden = (const float*)d_in[0];
    const int*   morpho = (const int*)d_in[1];
    const float* Wq = (const float*)d_in[2];
    const float* bq = (const float*)d_in[3];
    const float* Wk = (const float*)d_in[4];
    const float* bk = (const float*)d_in[5];
    const float* Wv = (const float*)d_in[6];
    const float* bv = (const float*)d_in[7];
    const float* Wo = (const float*)d_in[8];
    const float* bo = (const float*)d_in[9];
    float* out = (float*)d_out;

    cudaFuncSetAttribute(qkv_tc,
                         cudaFuncAttributeMaxDynamicSharedMemorySize, GT_SMEM_BYTES);
    cudaFuncSetAttribute(out_tc,
                         cudaFuncAttributeMaxDynamicSharedMemorySize, GT_SMEM_BYTES);
    cudaFuncSetAttribute(attn_mma,
                         cudaFuncAttributeMaxDynamicSharedMemorySize, AT_SMEM);

    static __half *xh_p = nullptr;
    if (!xh_p) {
        cudaGetSymbolAddress((void**)&xh_p, g_xh);
    }

    morpho_kernel<<<Bn, Sn>>>(morpho);
    convert_half<<<(Mtot*Hn/4 + 255) / 256, 256>>>(hidden, xh_p, Mtot*Hn);
    transpose_convert_w<<<dim3(32, 32, 4), dim3(32, 8)>>>(Wq, Wk, Wv, Wo);
    qkv_tc<<<dim3(Hn/128, Mtot/128, 3), 256, GT_SMEM_BYTES>>>(bq, bk, bv);
    attn_mma<<<dim3(Sn/128, NHn, Bn), 256, AT_SMEM>>>();
    out_tc<<<dim3(Hn/128, Mtot/128, 1), 256, GT_SMEM_BYTES>>>(bo, out);
}

// round 15
// speedup vs baseline: 2.6124x; 1.2071x over previous
#include <cuda_runtime.h>
#include <cuda_fp16.h>
#include <cstdint>

#define Bn 4
#define Sn 1024
#define Hn 1024
#define NHn 16
#define HDn 64
#define LOG2E 1.4426950408889634f
#define SCALE_L2E (0.125f * 1.4426950408889634f)
#define VERB_L2E (2.0f * 1.4426950408889634f)

#define Mtot (Bn*Sn)     // 4096
#define W_ELEMS (Hn*Hn)  // 1048576

// ---------------- scratch (allocation-free) ----------------
__device__ float g_colb[Bn*Sn];
__device__ int   g_vt[Bn*Sn];

__device__ __half g_xh [Mtot*Hn];     // hidden, single fp16
__device__ __half g_q1 [Mtot*Hn];     // Q single fp16
__device__ __half g_k1 [Mtot*Hn];     // K single fp16
__device__ __half g_v1 [Mtot*Hn];     // V single fp16
__device__ __half g_o1 [Mtot*Hn];     // attention output single fp16
__device__ __half g_wthi[4*W_ELEMS];  // W^T per matrix: [n][k]
__device__ __half g_wtlo[4*W_ELEMS];

// ---------------- PTX helpers (family-portable only) ----------------
__device__ __forceinline__ uint32_t smem_to_u32(const void* p) {
    uint32_t a;
    asm("{ .reg .u64 t; cvta.to.shared.u64 t, %1; cvt.u32.u64 %0, t; }" : "=r"(a) : "l"(p));
    return a;
}
__device__ __forceinline__ void ldsm_x4(uint32_t addr, uint32_t& r0, uint32_t& r1,
                                        uint32_t& r2, uint32_t& r3) {
    asm volatile("ldmatrix.sync.aligned.m8n8.x4.shared.b16 {%0,%1,%2,%3}, [%4];"
        : "=r"(r0), "=r"(r1), "=r"(r2), "=r"(r3) : "r"(addr));
}
__device__ __forceinline__ void ldsm_x4_t(uint32_t addr, uint32_t& r0, uint32_t& r1,
                                          uint32_t& r2, uint32_t& r3) {
    asm volatile("ldmatrix.sync.aligned.m8n8.x4.trans.shared.b16 {%0,%1,%2,%3}, [%4];"
        : "=r"(r0), "=r"(r1), "=r"(r2), "=r"(r3) : "r"(addr));
}
__device__ __forceinline__ void mma16816(float* c, uint32_t a0, uint32_t a1,
                                         uint32_t a2, uint32_t a3,
                                         uint32_t b0, uint32_t b1) {
    asm volatile(
        "mma.sync.aligned.m16n8k16.row.col.f32.f16.f16.f32 "
        "{%0,%1,%2,%3}, {%4,%5,%6,%7}, {%8,%9}, {%0,%1,%2,%3};"
        : "+f"(c[0]), "+f"(c[1]), "+f"(c[2]), "+f"(c[3])
        : "r"(a0), "r"(a1), "r"(a2), "r"(a3), "r"(b0), "r"(b1));
}
__device__ __forceinline__ void cp_async16(uint32_t saddr, const void* gptr) {
    asm volatile("cp.async.cg.shared.global [%0], [%1], 16;" :: "r"(saddr), "l"(gptr));
}
#define CP_COMMIT() asm volatile("cp.async.commit_group;")
#define CP_WAIT0()  asm volatile("cp.async.wait_group 0;")
#define CP_WAIT1()  asm volatile("cp.async.wait_group 1;")

__device__ __forceinline__ float ex2f(float x) {
    float y;
    asm("ex2.approx.ftz.f32 %0, %1;" : "=f"(y) : "f"(x));
    return y;
}

// SW128 swizzled address within a tile of 128B rows
__device__ __forceinline__ uint32_t swz(uint32_t base, int row, int kb) {
    uint32_t bo = (uint32_t)(row * 128 + kb);
    return base + (bo ^ ((bo >> 3) & 0x70));
}
__device__ __forceinline__ uint32_t swzoff(int row, int kb) {
    uint32_t bo = (uint32_t)(row * 128 + kb);
    return bo ^ ((bo >> 3) & 0x70);
}
__device__ __forceinline__ uint32_t pack_f16(float a, float b) {
    __half2 h = __floats2half2_rn(a, b);
    return *(uint32_t*)&h;
}

// ---------------- morpho preprocessing ----------------
__global__ void morpho_kernel(const int* __restrict__ morpho) {
    int b = blockIdx.x;
    int i = threadIdx.x;
    const int* mrow = morpho + b * Sn;
    __shared__ unsigned char isv[Sn];
    __shared__ int anyv;
    if (i == 0) anyv = 0;
    __syncthreads();
    int t = mrow[i];
    unsigned char iv = (t == 2);
    isv[i] = iv;
    if (iv) anyv = 1;
    g_colb[b*Sn + i] = (1.5f*0.5f) * (t == 0) + (1.2f*0.3f) * (t == 1);
    __syncthreads();
    int nearest = -1;
    if (anyv) {
        for (int d = 0; d < Sn; d++) {
            int jl = i - d;
            if (jl >= 0 && isv[jl]) { nearest = jl; break; }
            int jr = i + d;
            if (jr < Sn && isv[jr]) { nearest = jr; break; }
        }
    }
    g_vt[b*Sn + i] = nearest;
}

// ---------------- conversion kernels ----------------
__global__ void convert_half(const float* __restrict__ src,
                             __half* __restrict__ hi, int n) {
    int idx = (blockIdx.x * blockDim.x + threadIdx.x) * 4;
    if (idx < n) {
        float4 x = *(const float4*)(src + idx);
        *(__half2*)(hi + idx)     = __floats2half2_rn(x.x, x.y);
        *(__half2*)(hi + idx + 2) = __floats2half2_rn(x.z, x.w);
    }
}

__global__ void transpose_convert_w(const float* __restrict__ Wq, const float* __restrict__ Wk,
                                    const float* __restrict__ Wv, const float* __restrict__ Wo) {
    __shared__ float t[32][33];
    int z = blockIdx.z;
    const float* W = (z == 0) ? Wq : (z == 1) ? Wk : (z == 2) ? Wv : Wo;
    __half* whi = g_wthi + (size_t)z * W_ELEMS;
    __half* wlo = g_wtlo + (size_t)z * W_ELEMS;
    int n0 = blockIdx.x * 32, k0 = blockIdx.y * 32;
    int tx = threadIdx.x, ty = threadIdx.y;
    #pragma unroll
    for (int i = 0; i < 4; i++) {
        int kr = ty + i * 8;
        t[kr][tx] = W[(size_t)(k0 + kr) * Hn + n0 + tx];
    }
    __syncthreads();
    #pragma unroll
    for (int i = 0; i < 4; i++) {
        int nr = ty + i * 8;
        float x = t[tx][nr];
        __half h = __float2half_rn(x);
        whi[(size_t)(n0 + nr) * Hn + k0 + tx] = h;
        wlo[(size_t)(n0 + nr) * Hn + k0 + tx] = __float2half_rn(x - __half2float(h));
    }
}

// ---------------- mma.sync GEMM: NPASS in {1,2}, 2-stage cp.async ----------------
// Stage = A(16K) + Bhi(16K) [+ Blo(16K)] ; buffers fixed at 48KB/stage for layout simplicity.
// OUTMODE: 0 = fp32 C + bias, 2 = half single
#define GT_TILE 16384
#define GT_BUF  (3*GT_TILE)          // 49152 per stage
#define GT_SMEM_BYTES (2*GT_BUF)     // 98304
#define NCHUNK 16

template<int NPASS, int OUTMODE>
__device__ __forceinline__ void gemm_mma_body(
    const __half* __restrict__ A,
    const __half* __restrict__ Bhi, const __half* __restrict__ Blo,
    const float* __restrict__ bias, float* __restrict__ C,
    __half* __restrict__ Ch)
{
    extern __shared__ char smc[];
    uint32_t smb = smem_to_u32(smc);

    int tid = threadIdx.x;
    int wid = tid >> 5, lane = tid & 31;
    int r0 = blockIdx.y * 128;
    int c0 = blockIdx.x * 128;
    int wm = (wid >> 2) * 64;
    int wn = (wid & 3) * 32;

    int la = lane & 7, qa = lane >> 3;
    int rowoff_a = (qa & 1) * 8 + la;
    int kboff_a  = (qa >> 1) * 16;
    int rowoff_b = (qa >> 1) * 8 + la;
    int kboff_b  = (qa & 1) * 16;

    float acc[4][4][4];
    #pragma unroll
    for (int mf = 0; mf < 4; mf++)
        #pragma unroll
        for (int nf = 0; nf < 4; nf++)
            #pragma unroll
            for (int j = 0; j < 4; j++) acc[mf][nf][j] = 0.f;

    auto issue_chunk = [&](uint32_t base, int kk0) {
        #pragma unroll
        for (int r = 0; r < 4; r++) {
            int idx = tid + 256 * r;
            int row = idx >> 3, c16 = idx & 7;
            uint32_t sw = swzoff(row, c16 * 16);
            size_t ga = (size_t)(r0 + row) * Hn + kk0 + c16 * 8;
            size_t gb = (size_t)(c0 + row) * Hn + kk0 + c16 * 8;
            cp_async16(base + sw,             A + ga);
            cp_async16(base + GT_TILE + sw,   Bhi + gb);
            if (NPASS == 2) cp_async16(base + 2*GT_TILE + sw, Blo + gb);
        }
        CP_COMMIT();
    };

    issue_chunk(smb, 0);

    for (int ch = 0; ch < NCHUNK; ch++) {
        if (ch + 1 < NCHUNK) {
            issue_chunk(smb + (uint32_t)((ch + 1) & 1) * GT_BUF, (ch + 1) * 64);
            CP_WAIT1();
        } else {
            CP_WAIT0();
        }
        __syncthreads();

        uint32_t cb = smb + (uint32_t)(ch & 1) * GT_BUF;
        uint32_t tA = cb, tBhi = cb + GT_TILE, tBlo = cb + 2*GT_TILE;

        #pragma unroll
        for (int ks = 0; ks < 4; ks++) {
            int kb = ks * 32;
            uint32_t Ar[4][4], Bh[2][4], Bl[2][4];
            #pragma unroll
            for (int mf = 0; mf < 4; mf++) {
                int rw = wm + mf * 16 + rowoff_a;
                ldsm_x4(swz(tA, rw, kb + kboff_a), Ar[mf][0], Ar[mf][1], Ar[mf][2], Ar[mf][3]);
            }
            #pragma unroll
            for (int g = 0; g < 2; g++) {
                int rwb = wn + g * 16 + rowoff_b;
                ldsm_x4(swz(tBhi, rwb, kb + kboff_b), Bh[g][0], Bh[g][1], Bh[g][2], Bh[g][3]);
                if (NPASS == 2)
                    ldsm_x4(swz(tBlo, rwb, kb + kboff_b), Bl[g][0], Bl[g][1], Bl[g][2], Bl[g][3]);
            }
            #pragma unroll
            for (int mf = 0; mf < 4; mf++)
                #pragma unroll
                for (int nf = 0; nf < 4; nf++)
                    mma16816(acc[mf][nf], Ar[mf][0], Ar[mf][1], Ar[mf][2], Ar[mf][3],
                             Bh[nf >> 1][(nf & 1) * 2], Bh[nf >> 1][(nf & 1) * 2 + 1]);
            if (NPASS == 2) {
                #pragma unroll
                for (int mf = 0; mf < 4; mf++)
                    #pragma unroll
                    for (int nf = 0; nf < 4; nf++)
                        mma16816(acc[mf][nf], Ar[mf][0], Ar[mf][1], Ar[mf][2], Ar[mf][3],
                                 Bl[nf >> 1][(nf & 1) * 2], Bl[nf >> 1][(nf & 1) * 2 + 1]);
            }
        }
        __syncthreads();
    }

    #pragma unroll
    for (int mf = 0; mf < 4; mf++) {
        int row = r0 + wm + mf * 16 + (lane >> 2);
        #pragma unroll
        for (int nf = 0; nf < 4; nf++) {
            int col = c0 + wn + nf * 8 + 2 * (lane & 3);
            float b0 = bias[col], b1 = bias[col + 1];
            float v0 = acc[mf][nf][0] + b0, v1 = acc[mf][nf][1] + b1;
            float v2 = acc[mf][nf][2] + b0, v3 = acc[mf][nf][3] + b1;
            if (OUTMODE == 2) {
                *(__half2*)(Ch + (size_t)row * Hn + col)       = __floats2half2_rn(v0, v1);
                *(__half2*)(Ch + (size_t)(row + 8) * Hn + col) = __floats2half2_rn(v2, v3);
            } else {
                *(float2*)(C + (size_t)row * Hn + col)       = make_float2(v0, v1);
                *(float2*)(C + (size_t)(row + 8) * Hn + col) = make_float2(v2, v3);
            }
        }
    }
}

__global__ void __launch_bounds__(256, 1) qkv_tc(
    const float* __restrict__ bq, const float* __restrict__ bk, const float* __restrict__ bv)
{
    int z = blockIdx.z;
    if (z == 0) {
        // Q: 1-pass (softmax-attenuated path)
        gemm_mma_body<1, 2>(g_xh, g_wthi, nullptr, bq, nullptr, g_q1);
    } else if (z == 1) {
        // K: 1-pass
        gemm_mma_body<1, 2>(g_xh, g_wthi + W_ELEMS, nullptr, bk, nullptr, g_k1);
    } else {
        // V: 2-pass (value path hits output directly)
        gemm_mma_body<2, 2>(g_xh, g_wthi + 2*(size_t)W_ELEMS, g_wtlo + 2*(size_t)W_ELEMS,
                            bv, nullptr, g_v1);
    }
}

__global__ void __launch_bounds__(256, 1) out_tc(const float* __restrict__ bo, float* __restrict__ C)
{
    gemm_mma_body<2, 0>(g_o1, g_wthi + 3*(size_t)W_ELEMS, g_wtlo + 3*(size_t)W_ELEMS,
                        bo, C, nullptr);
}

// ---------------- flash attention: all fp16 single; QK 1-pass; PV 1-pass ----------------
// CTA: 128 q-rows x (b,h), 256 threads / 8 warps. KV stage = K(8K)+V(8K) = 16KB.
#define AT_KVBUF 16384
#define AT_SMEM (4096 + 2*AT_KVBUF)  // 36864

__global__ void __launch_bounds__(256) attn_mma() {
    extern __shared__ char smc[];
    uint32_t smb = smem_to_u32(smc);
    float* colb_sm = (float*)smc;
    uint32_t bufb = smb + 4096;

    int tid = threadIdx.x;
    int wid = tid >> 5, lane = tid & 31;
    int b = blockIdx.z, h = blockIdx.y;
    int i0 = blockIdx.x * 128;

    int la = lane & 7, qa = lane >> 3;
    int roa = (qa & 1) * 8 + la, kba = (qa >> 1) * 16;   // A-style / trans-V style
    int rob = (qa >> 1) * 8 + la, kbb = (qa & 1) * 16;   // B-style (K)

    // stage colb pre-scaled by log2e
    #pragma unroll
    for (int r = 0; r < 4; r++)
        colb_sm[tid + 256 * r] = g_colb[b * Sn + tid + 256 * r] * LOG2E;

    // stage Q tile [128 x 64] into buffer region, extract to regs
    {
        const __half* qb = g_q1 + (size_t)(b * Sn + i0) * Hn + h * HDn;
        #pragma unroll
        for (int r = 0; r < 4; r++) {
            int idx = tid + 256 * r;
            int row = idx >> 3, c16 = idx & 7;
            uint32_t sw = swzoff(row, c16 * 16);
            *(uint4*)(smc + 4096 + sw) = *(const uint4*)(qb + (size_t)row * Hn + c16 * 8);
        }
    }
    __syncthreads();
    uint32_t Qh[4][4];
    #pragma unroll
    for (int kd = 0; kd < 4; kd++) {
        int rw = wid * 16 + roa;
        ldsm_x4(swz(bufb, rw, kd * 32 + kba), Qh[kd][0], Qh[kd][1], Qh[kd][2], Qh[kd][3]);
    }
    __syncthreads();   // ldmatrix done before cp.async overwrites region

    int r_g = i0 + wid * 16 + (lane >> 2);
    int vt0 = g_vt[b * Sn + r_g];
    int vt1 = g_vt[b * Sn + r_g + 8];

    float m0 = -3.0e38f, m1 = -3.0e38f, l0 = 0.f, l1 = 0.f;
    float acc[8][4];
    #pragma unroll
    for (int t = 0; t < 8; t++)
        #pragma unroll
        for (int j = 0; j < 4; j++) acc[t][j] = 0.f;

    const __half* kb0 = g_k1 + (size_t)b * Sn * Hn + h * HDn;
    const __half* vb0 = g_v1 + (size_t)b * Sn * Hn + h * HDn;

    auto issue_kv = [&](uint32_t base, int j0) {
        #pragma unroll
        for (int r = 0; r < 2; r++) {
            int idx = tid + 256 * r;
            int row = idx >> 3, c16 = idx & 7;
            uint32_t sw = swzoff(row, c16 * 16);
            size_t go = (size_t)(j0 + row) * Hn + c16 * 8;
            cp_async16(base + sw,        kb0 + go);
            cp_async16(base + 8192 + sw, vb0 + go);
        }
        CP_COMMIT();
    };

    issue_kv(bufb, 0);

    for (int jt = 0; jt < Sn / 64; jt++) {
        if (jt + 1 < Sn / 64) {
            issue_kv(bufb + ((jt + 1) & 1) * AT_KVBUF, (jt + 1) * 64);
            CP_WAIT1();
        } else {
            CP_WAIT0();
        }
        __syncthreads();

        uint32_t cb = bufb + (jt & 1) * AT_KVBUF;
        uint32_t Kt = cb, Vt = cb + 8192;

        // S = Q K^T (1 pass, single fp16)
        float s[8][4];
        #pragma unroll
        for (int t = 0; t < 8; t++)
            #pragma unroll
            for (int j = 0; j < 4; j++) s[t][j] = 0.f;
        #pragma unroll
        for (int kd = 0; kd < 4; kd++) {
            #pragma unroll
            for (int ng = 0; ng < 4; ng++) {
                uint32_t kh[4];
                ldsm_x4(swz(Kt, ng * 16 + rob, kd * 32 + kbb), kh[0], kh[1], kh[2], kh[3]);
                mma16816(s[2*ng],   Qh[kd][0], Qh[kd][1], Qh[kd][2], Qh[kd][3], kh[0], kh[1]);
                mma16816(s[2*ng+1], Qh[kd][0], Qh[kd][1], Qh[kd][2], Qh[kd][3], kh[2], kh[3]);
            }
        }

        // scale + bias (log2 domain) + online softmax
        float rmax0 = -3.0e38f, rmax1 = -3.0e38f;
        #pragma unroll
        for (int t = 0; t < 8; t++) {
            int jc = jt * 64 + t * 8 + (lane & 3) * 2;
            float cb0 = colb_sm[jc], cb1 = colb_sm[jc + 1];
            s[t][0] = s[t][0] * SCALE_L2E + cb0 + (jc     == vt0 ? VERB_L2E : 0.f);
            s[t][1] = s[t][1] * SCALE_L2E + cb1 + (jc + 1 == vt0 ? VERB_L2E : 0.f);
            s[t][2] = s[t][2] * SCALE_L2E + cb0 + (jc     == vt1 ? VERB_L2E : 0.f);
            s[t][3] = s[t][3] * SCALE_L2E + cb1 + (jc + 1 == vt1 ? VERB_L2E : 0.f);
            rmax0 = fmaxf(rmax0, fmaxf(s[t][0], s[t][1]));
            rmax1 = fmaxf(rmax1, fmaxf(s[t][2], s[t][3]));
        }
        rmax0 = fmaxf(rmax0, __shfl_xor_sync(0xffffffffu, rmax0, 1));
        rmax0 = fmaxf(rmax0, __shfl_xor_sync(0xffffffffu, rmax0, 2));
        rmax1 = fmaxf(rmax1, __shfl_xor_sync(0xffffffffu, rmax1, 1));
        rmax1 = fmaxf(rmax1, __shfl_xor_sync(0xffffffffu, rmax1, 2));
        float mn0 = fmaxf(m0, rmax0), mn1 = fmaxf(m1, rmax1);
        float cr0 = ex2f(m0 - mn0), cr1 = ex2f(m1 - mn1);
        m0 = mn0; m1 = mn1;

        float sum0 = 0.f, sum1 = 0.f;
        uint32_t Ph[4][4];
        #pragma unroll
        for (int g = 0; g < 4; g++) {
            #pragma unroll
            for (int hh = 0; hh < 2; hh++) {
                int t = 2 * g + hh;
                float p0 = ex2f(s[t][0] - mn0);
                float p1 = ex2f(s[t][1] - mn0);
                float p2 = ex2f(s[t][2] - mn1);
                float p3 = ex2f(s[t][3] - mn1);
                sum0 += p0 + p1; sum1 += p2 + p3;
                Ph[g][hh * 2]     = pack_f16(p0, p1);
                Ph[g][hh * 2 + 1] = pack_f16(p2, p3);
            }
        }
        sum0 += __shfl_xor_sync(0xffffffffu, sum0, 1);
        sum0 += __shfl_xor_sync(0xffffffffu, sum0, 2);
        sum1 += __shfl_xor_sync(0xffffffffu, sum1, 1);
        sum1 += __shfl_xor_sync(0xffffffffu, sum1, 2);
        l0 = l0 * cr0 + sum0;
        l1 = l1 * cr1 + sum1;
        #pragma unroll
        for (int t = 0; t < 8; t++) {
            acc[t][0] *= cr0; acc[t][1] *= cr0;
            acc[t][2] *= cr1; acc[t][3] *= cr1;
        }

        // O += P V  (1 pass, single fp16 P and V): 2 MMAs per (g,gd)
        #pragma unroll
        for (int g = 0; g < 4; g++) {
            #pragma unroll
            for (int gd = 0; gd < 4; gd++) {
                uint32_t vh[4];
                ldsm_x4_t(swz(Vt, g * 16 + roa, gd * 32 + kba), vh[0], vh[1], vh[2], vh[3]);
                mma16816(acc[2*gd],   Ph[g][0], Ph[g][1], Ph[g][2], Ph[g][3], vh[0], vh[1]);
                mma16816(acc[2*gd+1], Ph[g][0], Ph[g][1], Ph[g][2], Ph[g][3], vh[2], vh[3]);
            }
        }
        __syncthreads();
    }

    // epilogue: normalize, store single fp16
    float inv0 = 1.f / l0, inv1 = 1.f / l1;
    __half* ob = g_o1 + (size_t)(b * Sn + r_g) * Hn + h * HDn;
    #pragma unroll
    for (int t = 0; t < 8; t++) {
        int d = t * 8 + (lane & 3) * 2;
        *(__half2*)(ob + d) =
            __floats2half2_rn(acc[t][0] * inv0, acc[t][1] * inv0);
        *(__half2*)(ob + (size_t)8 * Hn + d) =
            __floats2half2_rn(acc[t][2] * inv1, acc[t][3] * inv1);
    }
}

// ---------------- launch ----------------
extern "C" void kernel_launch(void* const* d_in, const int* in_sizes, int n_in,
                              void* d_out, int out_size) {
    const float* hidden = (const float*)d_in[0];
    const int*   morpho = (const int*)d_in[1];
    const float* Wq = (const float*)d_in[2];
    const float* bq = (const float*)d_in[3];
    const float* Wk = (const float*)d_in[4];
    const float* bk = (const float*)d_in[5];
    const float* Wv = (const float*)d_in[6];
    const float* bv = (const float*)d_in[7];
    const float* Wo = (const float*)d_in[8];
    const float* bo = (const float*)d_in[9];
    float* out = (float*)d_out;

    cudaFuncSetAttribute(qkv_tc,
                         cudaFuncAttributeMaxDynamicSharedMemorySize, GT_SMEM_BYTES);
    cudaFuncSetAttribute(out_tc,
                         cudaFuncAttributeMaxDynamicSharedMemorySize, GT_SMEM_BYTES);
    cudaFuncSetAttribute(attn_mma,
                         cudaFuncAttributeMaxDynamicSharedMemorySize, AT_SMEM);

    static __half *xh_p = nullptr;
    if (!xh_p) {
        cudaGetSymbolAddress((void**)&xh_p, g_xh);
    }

    morpho_kernel<<<Bn, Sn>>>(morpho);
    convert_half<<<(Mtot*Hn/4 + 255) / 256, 256>>>(hidden, xh_p, Mtot*Hn);
    transpose_convert_w<<<dim3(32, 32, 4), dim3(32, 8)>>>(Wq, Wk, Wv, Wo);
    qkv_tc<<<dim3(Hn/128, Mtot/128, 3), 256, GT_SMEM_BYTES>>>(bq, bk, bv);
    attn_mma<<<dim3(Sn/128, NHn, Bn), 256, AT_SMEM>>>();
    out_tc<<<dim3(Hn/128, Mtot/128, 1), 256, GT_SMEM_BYTES>>>(bo, out);
}

// round 16
// speedup vs baseline: 3.0494x; 1.1673x over previous
#include <cuda_runtime.h>
#include <cuda_fp16.h>
#include <cstdint>

#define Bn 4
#define Sn 1024
#define Hn 1024
#define NHn 16
#define HDn 64
#define LOG2E 1.4426950408889634f
#define SCALE_L2E (0.125f * 1.4426950408889634f)
#define VERB_L2E (2.0f * 1.4426950408889634f)

#define Mtot (Bn*Sn)     // 4096
#define W_ELEMS (Hn*Hn)  // 1048576

// ---------------- scratch (allocation-free) ----------------
__device__ float g_colb[Bn*Sn];
__device__ int   g_vt[Bn*Sn];

__device__ __half g_xh [Mtot*Hn];     // hidden, single fp16
__device__ __half g_q1 [Mtot*Hn];     // Q single fp16
__device__ __half g_k1 [Mtot*Hn];     // K single fp16
__device__ __half g_v1 [Mtot*Hn];     // V single fp16
__device__ __half g_o1 [Mtot*Hn];     // attention output single fp16
__device__ __half g_wt [4*W_ELEMS];   // W^T per matrix: [n][k], single fp16

// ---------------- PTX helpers (family-portable only) ----------------
__device__ __forceinline__ uint32_t smem_to_u32(const void* p) {
    uint32_t a;
    asm("{ .reg .u64 t; cvta.to.shared.u64 t, %1; cvt.u32.u64 %0, t; }" : "=r"(a) : "l"(p));
    return a;
}
__device__ __forceinline__ void ldsm_x4(uint32_t addr, uint32_t& r0, uint32_t& r1,
                                        uint32_t& r2, uint32_t& r3) {
    asm volatile("ldmatrix.sync.aligned.m8n8.x4.shared.b16 {%0,%1,%2,%3}, [%4];"
        : "=r"(r0), "=r"(r1), "=r"(r2), "=r"(r3) : "r"(addr));
}
__device__ __forceinline__ void ldsm_x4_t(uint32_t addr, uint32_t& r0, uint32_t& r1,
                                          uint32_t& r2, uint32_t& r3) {
    asm volatile("ldmatrix.sync.aligned.m8n8.x4.trans.shared.b16 {%0,%1,%2,%3}, [%4];"
        : "=r"(r0), "=r"(r1), "=r"(r2), "=r"(r3) : "r"(addr));
}
__device__ __forceinline__ void mma16816(float* c, uint32_t a0, uint32_t a1,
                                         uint32_t a2, uint32_t a3,
                                         uint32_t b0, uint32_t b1) {
    asm volatile(
        "mma.sync.aligned.m16n8k16.row.col.f32.f16.f16.f32 "
        "{%0,%1,%2,%3}, {%4,%5,%6,%7}, {%8,%9}, {%0,%1,%2,%3};"
        : "+f"(c[0]), "+f"(c[1]), "+f"(c[2]), "+f"(c[3])
        : "r"(a0), "r"(a1), "r"(a2), "r"(a3), "r"(b0), "r"(b1));
}
__device__ __forceinline__ void cp_async16(uint32_t saddr, const void* gptr) {
    asm volatile("cp.async.cg.shared.global [%0], [%1], 16;" :: "r"(saddr), "l"(gptr));
}
#define CP_COMMIT() asm volatile("cp.async.commit_group;")
#define CP_WAIT0()  asm volatile("cp.async.wait_group 0;")
#define CP_WAIT1()  asm volatile("cp.async.wait_group 1;")

__device__ __forceinline__ float ex2f(float x) {
    float y;
    asm("ex2.approx.ftz.f32 %0, %1;" : "=f"(y) : "f"(x));
    return y;
}

// SW128 swizzled address within a tile of 128B rows
__device__ __forceinline__ uint32_t swz(uint32_t base, int row, int kb) {
    uint32_t bo = (uint32_t)(row * 128 + kb);
    return base + (bo ^ ((bo >> 3) & 0x70));
}
__device__ __forceinline__ uint32_t swzoff(int row, int kb) {
    uint32_t bo = (uint32_t)(row * 128 + kb);
    return bo ^ ((bo >> 3) & 0x70);
}
__device__ __forceinline__ uint32_t pack_f16(float a, float b) {
    __half2 h = __floats2half2_rn(a, b);
    return *(uint32_t*)&h;
}

// ---------------- morpho preprocessing ----------------
__global__ void morpho_kernel(const int* __restrict__ morpho) {
    int b = blockIdx.x;
    int i = threadIdx.x;
    const int* mrow = morpho + b * Sn;
    __shared__ unsigned char isv[Sn];
    __shared__ int anyv;
    if (i == 0) anyv = 0;
    __syncthreads();
    int t = mrow[i];
    unsigned char iv = (t == 2);
    isv[i] = iv;
    if (iv) anyv = 1;
    g_colb[b*Sn + i] = (1.5f*0.5f) * (t == 0) + (1.2f*0.3f) * (t == 1);
    __syncthreads();
    int nearest = -1;
    if (anyv) {
        for (int d = 0; d < Sn; d++) {
            int jl = i - d;
            if (jl >= 0 && isv[jl]) { nearest = jl; break; }
            int jr = i + d;
            if (jr < Sn && isv[jr]) { nearest = jr; break; }
        }
    }
    g_vt[b*Sn + i] = nearest;
}

// ---------------- conversion kernels ----------------
__global__ void convert_half(const float* __restrict__ src,
                             __half* __restrict__ hi, int n) {
    int idx = (blockIdx.x * blockDim.x + threadIdx.x) * 4;
    if (idx < n) {
        float4 x = *(const float4*)(src + idx);
        *(__half2*)(hi + idx)     = __floats2half2_rn(x.x, x.y);
        *(__half2*)(hi + idx + 2) = __floats2half2_rn(x.z, x.w);
    }
}

__global__ void transpose_convert_w(const float* __restrict__ Wq, const float* __restrict__ Wk,
                                    const float* __restrict__ Wv, const float* __restrict__ Wo) {
    __shared__ float t[32][33];
    int z = blockIdx.z;
    const float* W = (z == 0) ? Wq : (z == 1) ? Wk : (z == 2) ? Wv : Wo;
    __half* wt = g_wt + (size_t)z * W_ELEMS;
    int n0 = blockIdx.x * 32, k0 = blockIdx.y * 32;
    int tx = threadIdx.x, ty = threadIdx.y;
    #pragma unroll
    for (int i = 0; i < 4; i++) {
        int kr = ty + i * 8;
        t[kr][tx] = W[(size_t)(k0 + kr) * Hn + n0 + tx];
    }
    __syncthreads();
    #pragma unroll
    for (int i = 0; i < 4; i++) {
        int nr = ty + i * 8;
        wt[(size_t)(n0 + nr) * Hn + k0 + tx] = __float2half_rn(t[tx][nr]);
    }
}

// ---------------- mma.sync GEMM: 1-pass fp16, 2-stage cp.async, K-chunk 64 ----------------
// Stage = A(16K) + B(16K) = 32KB; 2 stages = 64KB.
// OUTMODE: 0 = fp32 C + bias, 2 = half single
#define GT_TILE 16384
#define GT_BUF  (2*GT_TILE)          // 32768 per stage
#define GT_SMEM_BYTES (2*GT_BUF)     // 65536
#define NCHUNK 16

template<int OUTMODE>
__device__ __forceinline__ void gemm_mma_body(
    const __half* __restrict__ A,
    const __half* __restrict__ Bm,
    const float* __restrict__ bias, float* __restrict__ C,
    __half* __restrict__ Ch)
{
    extern __shared__ char smc[];
    uint32_t smb = smem_to_u32(smc);

    int tid = threadIdx.x;
    int wid = tid >> 5, lane = tid & 31;
    int r0 = blockIdx.y * 128;
    int c0 = blockIdx.x * 128;
    int wm = (wid >> 2) * 64;
    int wn = (wid & 3) * 32;

    int la = lane & 7, qa = lane >> 3;
    int rowoff_a = (qa & 1) * 8 + la;
    int kboff_a  = (qa >> 1) * 16;
    int rowoff_b = (qa >> 1) * 8 + la;
    int kboff_b  = (qa & 1) * 16;

    float acc[4][4][4];
    #pragma unroll
    for (int mf = 0; mf < 4; mf++)
        #pragma unroll
        for (int nf = 0; nf < 4; nf++)
            #pragma unroll
            for (int j = 0; j < 4; j++) acc[mf][nf][j] = 0.f;

    auto issue_chunk = [&](uint32_t base, int kk0) {
        #pragma unroll
        for (int r = 0; r < 4; r++) {
            int idx = tid + 256 * r;
            int row = idx >> 3, c16 = idx & 7;
            uint32_t sw = swzoff(row, c16 * 16);
            size_t ga = (size_t)(r0 + row) * Hn + kk0 + c16 * 8;
            size_t gb = (size_t)(c0 + row) * Hn + kk0 + c16 * 8;
            cp_async16(base + sw,           A + ga);
            cp_async16(base + GT_TILE + sw, Bm + gb);
        }
        CP_COMMIT();
    };

    issue_chunk(smb, 0);

    for (int ch = 0; ch < NCHUNK; ch++) {
        if (ch + 1 < NCHUNK) {
            issue_chunk(smb + (uint32_t)((ch + 1) & 1) * GT_BUF, (ch + 1) * 64);
            CP_WAIT1();
        } else {
            CP_WAIT0();
        }
        __syncthreads();

        uint32_t cb = smb + (uint32_t)(ch & 1) * GT_BUF;
        uint32_t tA = cb, tB = cb + GT_TILE;

        #pragma unroll
        for (int ks = 0; ks < 4; ks++) {
            int kb = ks * 32;
            uint32_t Ar[4][4], Br[2][4];
            #pragma unroll
            for (int mf = 0; mf < 4; mf++) {
                int rw = wm + mf * 16 + rowoff_a;
                ldsm_x4(swz(tA, rw, kb + kboff_a), Ar[mf][0], Ar[mf][1], Ar[mf][2], Ar[mf][3]);
            }
            #pragma unroll
            for (int g = 0; g < 2; g++) {
                int rwb = wn + g * 16 + rowoff_b;
                ldsm_x4(swz(tB, rwb, kb + kboff_b), Br[g][0], Br[g][1], Br[g][2], Br[g][3]);
            }
            #pragma unroll
            for (int mf = 0; mf < 4; mf++)
                #pragma unroll
                for (int nf = 0; nf < 4; nf++)
                    mma16816(acc[mf][nf], Ar[mf][0], Ar[mf][1], Ar[mf][2], Ar[mf][3],
                             Br[nf >> 1][(nf & 1) * 2], Br[nf >> 1][(nf & 1) * 2 + 1]);
        }
        __syncthreads();
    }

    #pragma unroll
    for (int mf = 0; mf < 4; mf++) {
        int row = r0 + wm + mf * 16 + (lane >> 2);
        #pragma unroll
        for (int nf = 0; nf < 4; nf++) {
            int col = c0 + wn + nf * 8 + 2 * (lane & 3);
            float b0 = bias[col], b1 = bias[col + 1];
            float v0 = acc[mf][nf][0] + b0, v1 = acc[mf][nf][1] + b1;
            float v2 = acc[mf][nf][2] + b0, v3 = acc[mf][nf][3] + b1;
            if (OUTMODE == 2) {
                *(__half2*)(Ch + (size_t)row * Hn + col)       = __floats2half2_rn(v0, v1);
                *(__half2*)(Ch + (size_t)(row + 8) * Hn + col) = __floats2half2_rn(v2, v3);
            } else {
                *(float2*)(C + (size_t)row * Hn + col)       = make_float2(v0, v1);
                *(float2*)(C + (size_t)(row + 8) * Hn + col) = make_float2(v2, v3);
            }
        }
    }
}

__global__ void __launch_bounds__(256, 1) qkv_tc(
    const float* __restrict__ bq, const float* __restrict__ bk, const float* __restrict__ bv)
{
    int z = blockIdx.z;
    const float* bias = (z == 0) ? bq : (z == 1) ? bk : bv;
    __half* Ch = (z == 0) ? g_q1 : (z == 1) ? g_k1 : g_v1;
    gemm_mma_body<2>(g_xh, g_wt + (size_t)z * W_ELEMS, bias, nullptr, Ch);
}

__global__ void __launch_bounds__(256, 1) out_tc(const float* __restrict__ bo, float* __restrict__ C)
{
    gemm_mma_body<0>(g_o1, g_wt + 3*(size_t)W_ELEMS, bo, C, nullptr);
}

// ---------------- flash attention: all fp16 single; QK 1-pass; PV 1-pass ----------------
// CTA: 128 q-rows x (b,h), 256 threads / 8 warps. KV stage = K(8K)+V(8K) = 16KB.
#define AT_KVBUF 16384
#define AT_SMEM (4096 + 2*AT_KVBUF)  // 36864

__global__ void __launch_bounds__(256) attn_mma() {
    extern __shared__ char smc[];
    uint32_t smb = smem_to_u32(smc);
    float* colb_sm = (float*)smc;
    uint32_t bufb = smb + 4096;

    int tid = threadIdx.x;
    int wid = tid >> 5, lane = tid & 31;
    int b = blockIdx.z, h = blockIdx.y;
    int i0 = blockIdx.x * 128;

    int la = lane & 7, qa = lane >> 3;
    int roa = (qa & 1) * 8 + la, kba = (qa >> 1) * 16;   // A-style / trans-V style
    int rob = (qa >> 1) * 8 + la, kbb = (qa & 1) * 16;   // B-style (K)

    // stage colb pre-scaled by log2e
    #pragma unroll
    for (int r = 0; r < 4; r++)
        colb_sm[tid + 256 * r] = g_colb[b * Sn + tid + 256 * r] * LOG2E;

    // stage Q tile [128 x 64] into buffer region, extract to regs
    {
        const __half* qb = g_q1 + (size_t)(b * Sn + i0) * Hn + h * HDn;
        #pragma unroll
        for (int r = 0; r < 4; r++) {
            int idx = tid + 256 * r;
            int row = idx >> 3, c16 = idx & 7;
            uint32_t sw = swzoff(row, c16 * 16);
            *(uint4*)(smc + 4096 + sw) = *(const uint4*)(qb + (size_t)row * Hn + c16 * 8);
        }
    }
    __syncthreads();
    uint32_t Qh[4][4];
    #pragma unroll
    for (int kd = 0; kd < 4; kd++) {
        int rw = wid * 16 + roa;
        ldsm_x4(swz(bufb, rw, kd * 32 + kba), Qh[kd][0], Qh[kd][1], Qh[kd][2], Qh[kd][3]);
    }
    __syncthreads();   // ldmatrix done before cp.async overwrites region

    int r_g = i0 + wid * 16 + (lane >> 2);
    int vt0 = g_vt[b * Sn + r_g];
    int vt1 = g_vt[b * Sn + r_g + 8];

    float m0 = -3.0e38f, m1 = -3.0e38f, l0 = 0.f, l1 = 0.f;
    float acc[8][4];
    #pragma unroll
    for (int t = 0; t < 8; t++)
        #pragma unroll
        for (int j = 0; j < 4; j++) acc[t][j] = 0.f;

    const __half* kb0 = g_k1 + (size_t)b * Sn * Hn + h * HDn;
    const __half* vb0 = g_v1 + (size_t)b * Sn * Hn + h * HDn;

    auto issue_kv = [&](uint32_t base, int j0) {
        #pragma unroll
        for (int r = 0; r < 2; r++) {
            int idx = tid + 256 * r;
            int row = idx >> 3, c16 = idx & 7;
            uint32_t sw = swzoff(row, c16 * 16);
            size_t go = (size_t)(j0 + row) * Hn + c16 * 8;
            cp_async16(base + sw,        kb0 + go);
            cp_async16(base + 8192 + sw, vb0 + go);
        }
        CP_COMMIT();
    };

    issue_kv(bufb, 0);

    for (int jt = 0; jt < Sn / 64; jt++) {
        if (jt + 1 < Sn / 64) {
            issue_kv(bufb + ((jt + 1) & 1) * AT_KVBUF, (jt + 1) * 64);
            CP_WAIT1();
        } else {
            CP_WAIT0();
        }
        __syncthreads();

        uint32_t cb = bufb + (jt & 1) * AT_KVBUF;
        uint32_t Kt = cb, Vt = cb + 8192;

        // S = Q K^T (1 pass, single fp16)
        float s[8][4];
        #pragma unroll
        for (int t = 0; t < 8; t++)
            #pragma unroll
            for (int j = 0; j < 4; j++) s[t][j] = 0.f;
        #pragma unroll
        for (int kd = 0; kd < 4; kd++) {
            #pragma unroll
            for (int ng = 0; ng < 4; ng++) {
                uint32_t kh[4];
                ldsm_x4(swz(Kt, ng * 16 + rob, kd * 32 + kbb), kh[0], kh[1], kh[2], kh[3]);
                mma16816(s[2*ng],   Qh[kd][0], Qh[kd][1], Qh[kd][2], Qh[kd][3], kh[0], kh[1]);
                mma16816(s[2*ng+1], Qh[kd][0], Qh[kd][1], Qh[kd][2], Qh[kd][3], kh[2], kh[3]);
            }
        }

        // scale + bias (log2 domain) + online softmax
        float rmax0 = -3.0e38f, rmax1 = -3.0e38f;
        #pragma unroll
        for (int t = 0; t < 8; t++) {
            int jc = jt * 64 + t * 8 + (lane & 3) * 2;
            float cb0 = colb_sm[jc], cb1 = colb_sm[jc + 1];
            s[t][0] = s[t][0] * SCALE_L2E + cb0 + (jc     == vt0 ? VERB_L2E : 0.f);
            s[t][1] = s[t][1] * SCALE_L2E + cb1 + (jc + 1 == vt0 ? VERB_L2E : 0.f);
            s[t][2] = s[t][2] * SCALE_L2E + cb0 + (jc     == vt1 ? VERB_L2E : 0.f);
            s[t][3] = s[t][3] * SCALE_L2E + cb1 + (jc + 1 == vt1 ? VERB_L2E : 0.f);
            rmax0 = fmaxf(rmax0, fmaxf(s[t][0], s[t][1]));
            rmax1 = fmaxf(rmax1, fmaxf(s[t][2], s[t][3]));
        }
        rmax0 = fmaxf(rmax0, __shfl_xor_sync(0xffffffffu, rmax0, 1));
        rmax0 = fmaxf(rmax0, __shfl_xor_sync(0xffffffffu, rmax0, 2));
        rmax1 = fmaxf(rmax1, __shfl_xor_sync(0xffffffffu, rmax1, 1));
        rmax1 = fmaxf(rmax1, __shfl_xor_sync(0xffffffffu, rmax1, 2));
        float mn0 = fmaxf(m0, rmax0), mn1 = fmaxf(m1, rmax1);
        float cr0 = ex2f(m0 - mn0), cr1 = ex2f(m1 - mn1);
        m0 = mn0; m1 = mn1;

        float sum0 = 0.f, sum1 = 0.f;
        uint32_t Ph[4][4];
        #pragma unroll
        for (int g = 0; g < 4; g++) {
            #pragma unroll
            for (int hh = 0; hh < 2; hh++) {
                int t = 2 * g + hh;
                float p0 = ex2f(s[t][0] - mn0);
                float p1 = ex2f(s[t][1] - mn0);
                float p2 = ex2f(s[t][2] - mn1);
                float p3 = ex2f(s[t][3] - mn1);
                sum0 += p0 + p1; sum1 += p2 + p3;
                Ph[g][hh * 2]     = pack_f16(p0, p1);
                Ph[g][hh * 2 + 1] = pack_f16(p2, p3);
            }
        }
        sum0 += __shfl_xor_sync(0xffffffffu, sum0, 1);
        sum0 += __shfl_xor_sync(0xffffffffu, sum0, 2);
        sum1 += __shfl_xor_sync(0xffffffffu, sum1, 1);
        sum1 += __shfl_xor_sync(0xffffffffu, sum1, 2);
        l0 = l0 * cr0 + sum0;
        l1 = l1 * cr1 + sum1;
        #pragma unroll
        for (int t = 0; t < 8; t++) {
            acc[t][0] *= cr0; acc[t][1] *= cr0;
            acc[t][2] *= cr1; acc[t][3] *= cr1;
        }

        // O += P V  (1 pass, single fp16 P and V): 2 MMAs per (g,gd)
        #pragma unroll
        for (int g = 0; g < 4; g++) {
            #pragma unroll
            for (int gd = 0; gd < 4; gd++) {
                uint32_t vh[4];
                ldsm_x4_t(swz(Vt, g * 16 + roa, gd * 32 + kba), vh[0], vh[1], vh[2], vh[3]);
                mma16816(acc[2*gd],   Ph[g][0], Ph[g][1], Ph[g][2], Ph[g][3], vh[0], vh[1]);
                mma16816(acc[2*gd+1], Ph[g][0], Ph[g][1], Ph[g][2], Ph[g][3], vh[2], vh[3]);
            }
        }
        __syncthreads();
    }

    // epilogue: normalize, store single fp16
    float inv0 = 1.f / l0, inv1 = 1.f / l1;
    __half* ob = g_o1 + (size_t)(b * Sn + r_g) * Hn + h * HDn;
    #pragma unroll
    for (int t = 0; t < 8; t++) {
        int d = t * 8 + (lane & 3) * 2;
        *(__half2*)(ob + d) =
            __floats2half2_rn(acc[t][0] * inv0, acc[t][1] * inv0);
        *(__half2*)(ob + (size_t)8 * Hn + d) =
            __floats2half2_rn(acc[t][2] * inv1, acc[t][3] * inv1);
    }
}

// ---------------- launch ----------------
extern "C" void kernel_launch(void* const* d_in, const int* in_sizes, int n_in,
                              void* d_out, int out_size) {
    const float* hidden = (const float*)d_in[0];
    const int*   morpho = (const int*)d_in[1];
    const float* Wq = (const float*)d_in[2];
    const float* bq = (const float*)d_in[3];
    const float* Wk = (const float*)d_in[4];
    const float* bk = (const float*)d_in[5];
    const float* Wv = (const float*)d_in[6];
    const float* bv = (const float*)d_in[7];
    const float* Wo = (const float*)d_in[8];
    const float* bo = (const float*)d_in[9];
    float* out = (float*)d_out;

    cudaFuncSetAttribute(qkv_tc,
                         cudaFuncAttributeMaxDynamicSharedMemorySize, GT_SMEM_BYTES);
    cudaFuncSetAttribute(out_tc,
                         cudaFuncAttributeMaxDynamicSharedMemorySize, GT_SMEM_BYTES);
    cudaFuncSetAttribute(attn_mma,
                         cudaFuncAttributeMaxDynamicSharedMemorySize, AT_SMEM);

    static __half *xh_p = nullptr;
    if (!xh_p) {
        cudaGetSymbolAddress((void**)&xh_p, g_xh);
    }

    morpho_kernel<<<Bn, Sn>>>(morpho);
    convert_half<<<(Mtot*Hn/4 + 255) / 256, 256>>>(hidden, xh_p, Mtot*Hn);
    transpose_convert_w<<<dim3(32, 32, 4), dim3(32, 8)>>>(Wq, Wk, Wv, Wo);
    qkv_tc<<<dim3(Hn/128, Mtot/128, 3), 256, GT_SMEM_BYTES>>>(bq, bk, bv);
    attn_mma<<<dim3(Sn/128, NHn, Bn), 256, AT_SMEM>>>();
    out_tc<<<dim3(Hn/128, Mtot/128, 1), 256, GT_SMEM_BYTES>>>(bo, out);
}